// round 8
// baseline (speedup 1.0000x reference)
#include <cuda_runtime.h>
#include <math.h>
#include <stdint.h>

#define NN   50000
#define NE   800000
#define FIN  1433
#define KPAD1 1440
#define FHID 256
#define FOUT 128
#define NCLS 7
#define BN_EPS 1e-5f

// ---------------- scratch (device globals; no runtime allocation) ----------------
__device__ int   g_cnt[NN];
__device__ int   g_offs[NN + 1];
__device__ int   g_cur[NN];
__device__ int   g_bsum[64];
__device__ int2  g_csr[NE];                     // (src, coef bits) packed
__device__ float g_dinv[NN];
__device__ float g_invdeg[NN];
__device__ float g_w1r[(size_t)KPAD1 * FHID];   // W1 [K,N] tf32-rounded, K zero-padded
__device__ float g_w2r[(size_t)FHID * FOUT];    // W2 [K,N] tf32-rounded
__device__ float g_h1[(size_t)NN * FHID];       // x @ W1
__device__ float g_act1[(size_t)NN * FHID];     // ELU(BN(agg1)), tf32-rounded
__device__ float g_h2[(size_t)NN * FOUT];       // act1 @ W2

// ================= helpers =================
__device__ __forceinline__ uint32_t smem_u32(const void* p) {
    uint32_t a;
    asm("{ .reg .u64 t; cvta.to.shared.u64 t, %1; cvt.u32.u64 %0, t; }" : "=r"(a) : "l"(p));
    return a;
}

__device__ __forceinline__ float tf32r(float x) {
    uint32_t u;
    asm("cvt.rna.tf32.f32 %0, %1;" : "=r"(u) : "f"(x));
    return __uint_as_float(u);
}

__device__ __forceinline__ uint32_t tf32u(uint32_t x) {
    uint32_t r;
    asm("cvt.rna.tf32.f32 %0, %1;" : "=r"(r) : "f"(__uint_as_float(x)));
    return r;
}

__device__ __forceinline__ void cp16(uint32_t dst, const void* src, int srcsize) {
    asm volatile("cp.async.cg.shared.global [%0], [%1], 16, %2;"
                 :: "r"(dst), "l"(src), "r"(srcsize) : "memory");
}

__device__ __forceinline__ void cp4(uint32_t dst, const void* src, int srcsize) {
    asm volatile("cp.async.ca.shared.global [%0], [%1], 4, %2;"
                 :: "r"(dst), "l"(src), "r"(srcsize) : "memory");
}

__device__ __forceinline__ void mma_tf32(float* c, const uint32_t* a, const uint32_t* b) {
    asm volatile(
        "mma.sync.aligned.m16n8k8.row.col.f32.tf32.tf32.f32 "
        "{%0,%1,%2,%3}, {%4,%5,%6,%7}, {%8,%9}, {%0,%1,%2,%3};"
        : "+f"(c[0]), "+f"(c[1]), "+f"(c[2]), "+f"(c[3])
        : "r"(a[0]), "r"(a[1]), "r"(a[2]), "r"(a[3]), "r"(b[0]), "r"(b[1]));
}

// ================= preprocessing =================
__global__ void round_w1_kernel(const float* __restrict__ W1) {
    int idx = blockIdx.x * blockDim.x + threadIdx.x;
    if (idx >= KPAD1 * FHID) return;
    int k = idx / FHID;
    g_w1r[idx] = (k < FIN) ? tf32r(W1[idx]) : 0.0f;
}

__global__ void round_w2_kernel(const float* __restrict__ W2) {
    int idx = blockIdx.x * blockDim.x + threadIdx.x;
    if (idx >= FHID * FOUT) return;
    g_w2r[idx] = tf32r(W2[idx]);
}

// ================= CSR build =================
__global__ void zero_cnt_kernel() {
    int i = blockIdx.x * blockDim.x + threadIdx.x;
    if (i < NN) g_cnt[i] = 0;
}

__global__ void count_deg_kernel(const int* __restrict__ dst) {
    int e = blockIdx.x * blockDim.x + threadIdx.x;
    if (e < NE) atomicAdd(&g_cnt[dst[e]], 1);
}

__global__ __launch_bounds__(1024)
void scan_block_kernel() {
    __shared__ int ws[32];
    int t = threadIdx.x, b = blockIdx.x;
    int i = b * 1024 + t;
    int v = (i < NN) ? g_cnt[i] : 0;
    if (i < NN) {
        float d = (float)v + 1.0f;
        g_dinv[i]   = rsqrtf(d);
        g_invdeg[i] = 1.0f / d;
    }
    int lane = t & 31, w = t >> 5;
    int x = v;
    #pragma unroll
    for (int o = 1; o < 32; o <<= 1) {
        int y = __shfl_up_sync(0xffffffffu, x, o);
        if (lane >= o) x += y;
    }
    if (lane == 31) ws[w] = x;
    __syncthreads();
    if (w == 0) {
        int s = ws[lane];
        #pragma unroll
        for (int o = 1; o < 32; o <<= 1) {
            int y = __shfl_up_sync(0xffffffffu, s, o);
            if (lane >= o) s += y;
        }
        ws[lane] = s;
    }
    __syncthreads();
    int pre = (w > 0) ? ws[w - 1] : 0;
    if (i < NN) g_offs[i] = pre + x - v;
    if (t == 1023) g_bsum[b] = pre + x;
}

__global__ void scan_bsum_kernel(int nblk) {
    __shared__ int s[64];
    int t = threadIdx.x;
    s[t] = (t < nblk) ? g_bsum[t] : 0;
    __syncthreads();
    if (t == 0) {
        int acc = 0;
        for (int i = 0; i < nblk; i++) { int v = s[i]; s[i] = acc; acc += v; }
    }
    __syncthreads();
    if (t < nblk) g_bsum[t] = s[t];
}

__global__ __launch_bounds__(1024)
void scan_add_kernel() {
    int t = threadIdx.x, b = blockIdx.x;
    int i = b * 1024 + t;
    if (i < NN) {
        int o = g_offs[i] + g_bsum[b];
        g_offs[i] = o;
        g_cur[i]  = o;
    }
    if (i == 0) g_offs[NN] = NE;
}

__global__ void fill_csr_kernel(const int* __restrict__ src, const int* __restrict__ dst) {
    int e = blockIdx.x * blockDim.x + threadIdx.x;
    if (e < NE) {
        int s = src[e];
        int d = dst[e];
        int p = atomicAdd(&g_cur[d], 1);
        g_csr[p] = make_int2(s, __float_as_int(g_dinv[s] * g_dinv[d]));
    }
}

// ================= tf32 mma.sync GEMM =================
// C[M, NMAT] = A[M, KA] @ B[KAceil16, NMAT].
// Block 128 x (WN*64); WM x WN warps; warp tile (128/WM) x 64.
// m16n8k8 tf32 mma, S-stage cp.async pipeline, 2 CTAs/SM via launch_bounds.
template <int NMAT, int KA, int KTILES, bool ALIGNED_A, bool ROUND_A, int WM, int WN>
__global__ __launch_bounds__(WM * WN * 32, 2)
void mma_gemm_kernel(const float* __restrict__ A, const float* __restrict__ B,
                     float* __restrict__ C) {
    constexpr int S = 4;
    constexpr int THREADS = WM * WN * 32;
    constexpr int BLOCKN = WN * 64;
    constexpr int MT = 128 / WM / 16;             // m16 subtiles per warp
    constexpr int AS_STRIDE = 20;
    constexpr int BS_STRIDE = BLOCKN + 8;         // ≡8 mod 32: bank-safe
    constexpr int A_FLOATS = 128 * AS_STRIDE;
    constexpr int B_FLOATS = 16 * BS_STRIDE;
    constexpr int STG = A_FLOATS + B_FLOATS;
    constexpr int FA = 2048 / THREADS;            // A floats per thread per stage
    constexpr int FB = 16 * BLOCKN / THREADS;     // B floats per thread per stage

    extern __shared__ float sm[];
    uint32_t smb = smem_u32(sm);

    int tid  = threadIdx.x;
    int lane = tid & 31;
    int w    = tid >> 5;
    int g    = lane >> 2;
    int tig  = lane & 3;
    int wm   = (w % WM) * (16 * MT);
    int wn   = (w / WM) * 64;
    int m0   = blockIdx.y * 128;
    int n0   = blockIdx.x * BLOCKN;

    int a_row  = tid / (16 / FA);
    int a_off  = (tid % (16 / FA)) * FA;
    int a_m    = m0 + a_row;
    bool a_ok  = (a_m < NN);
    const float* Ag = A + (size_t)(a_ok ? a_m : 0) * KA;
    uint32_t a_dst0 = smb + (uint32_t)(a_row * AS_STRIDE + a_off) * 4;

    constexpr int B_TPR = BLOCKN / FB;            // threads per B row
    int b_row = tid / B_TPR;
    int b_col = (tid % B_TPR) * FB;
    const float* Bg = B + (size_t)b_row * NMAT + n0 + b_col;
    uint32_t b_dst0 = smb + (uint32_t)(A_FLOATS + b_row * BS_STRIDE + b_col) * 4;

    float c[MT][8][4];
    #pragma unroll
    for (int mt = 0; mt < MT; mt++)
        #pragma unroll
        for (int nt = 0; nt < 8; nt++)
            #pragma unroll
            for (int q = 0; q < 4; q++) c[mt][nt][q] = 0.0f;

    auto load_a = [&](int kt, uint32_t off) {
        if (ALIGNED_A) {
            const float* ga = Ag + kt * 16 + a_off;
            int sz = a_ok ? 16 : 0;
            cp16(a_dst0 + off, ga, sz);
            if (FA == 8) cp16(a_dst0 + off + 16, ga + 4, sz);
        } else {
            int c0 = kt * 16 + a_off;
            #pragma unroll
            for (int i = 0; i < FA; i++) {
                int col = c0 + i;
                int sz = (a_ok && col < KA) ? 4 : 0;
                int cc = (col < KA) ? col : (KA - 1);
                cp4(a_dst0 + off + i * 4, Ag + cc, sz);
            }
        }
    };
    auto load_b = [&](int kt, uint32_t off) {
        const float* gb = Bg + (size_t)(kt * 16) * NMAT;
        #pragma unroll
        for (int i = 0; i < FB / 4; i++)
            cp16(b_dst0 + off + i * 16, gb + i * 4, 16);
    };

    #pragma unroll
    for (int s = 0; s < S - 1; s++) {
        uint32_t off = (uint32_t)(s * STG) * 4;
        if (s < KTILES) { load_a(s, off); load_b(s, off); }
        asm volatile("cp.async.commit_group;" ::: "memory");
    }

    for (int kt = 0; kt < KTILES; kt++) {
        asm volatile("cp.async.wait_group %0;" :: "n"(S - 2) : "memory");
        __syncthreads();

        {
            int nk = kt + S - 1;
            if (nk < KTILES) {
                uint32_t off = (uint32_t)((nk % S) * STG) * 4;
                load_a(nk, off);
                load_b(nk, off);
            }
            asm volatile("cp.async.commit_group;" ::: "memory");
        }

        const float* As = sm + (kt % S) * STG;
        const float* Bs = As + A_FLOATS;

        #pragma unroll
        for (int kk = 0; kk < 16; kk += 8) {
            uint32_t a[MT][4], b[8][2];
            #pragma unroll
            for (int mt = 0; mt < MT; mt++) {
                int r = wm + mt * 16 + g;
                a[mt][0] = __float_as_uint(As[r * AS_STRIDE + kk + tig]);
                a[mt][1] = __float_as_uint(As[(r + 8) * AS_STRIDE + kk + tig]);
                a[mt][2] = __float_as_uint(As[r * AS_STRIDE + kk + tig + 4]);
                a[mt][3] = __float_as_uint(As[(r + 8) * AS_STRIDE + kk + tig + 4]);
                if (ROUND_A) {
                    a[mt][0] = tf32u(a[mt][0]);
                    a[mt][1] = tf32u(a[mt][1]);
                    a[mt][2] = tf32u(a[mt][2]);
                    a[mt][3] = tf32u(a[mt][3]);
                }
            }
            #pragma unroll
            for (int nt = 0; nt < 8; nt++) {
                int ccol = wn + nt * 8 + g;
                b[nt][0] = __float_as_uint(Bs[(kk + tig) * BS_STRIDE + ccol]);
                b[nt][1] = __float_as_uint(Bs[(kk + tig + 4) * BS_STRIDE + ccol]);
            }
            #pragma unroll
            for (int mt = 0; mt < MT; mt++)
                #pragma unroll
                for (int nt = 0; nt < 8; nt++)
                    mma_tf32(c[mt][nt], a[mt], b[nt]);
        }
    }

    #pragma unroll
    for (int mt = 0; mt < MT; mt++) {
        int r0 = m0 + wm + mt * 16 + g;
        #pragma unroll
        for (int nt = 0; nt < 8; nt++) {
            int col = n0 + wn + nt * 8 + 2 * tig;
            if (r0 < NN)
                *(float2*)(C + (size_t)r0 * NMAT + col) = make_float2(c[mt][nt][0], c[mt][nt][1]);
            if (r0 + 8 < NN)
                *(float2*)(C + (size_t)(r0 + 8) * NMAT + col) = make_float2(c[mt][nt][2], c[mt][nt][3]);
        }
    }
}

// ================= fused aggregate + bias + BN + ELU (layer 1, F=256) =================
__device__ __forceinline__ float elu1(float x) { return x > 0.0f ? x : expm1f(x); }

__global__ __launch_bounds__(256)
void aggregate1_kernel(const float* __restrict__ bias,
                       const float* __restrict__ bnw, const float* __restrict__ bnb,
                       const float* __restrict__ bnm, const float* __restrict__ bnv) {
    const float* h = (const float*)g_h1;
    float* out = (float*)g_act1;
    constexpr int F = FHID;

    int warp = (blockIdx.x * blockDim.x + threadIdx.x) >> 5;
    int lane = threadIdx.x & 31;
    if (warp >= NN) return;
    int node = warp;

    float4 acc0, acc1;
    {
        const float4* hn = (const float4*)(h + (size_t)node * F);
        float idg = g_invdeg[node];
        float4 v0 = hn[lane], v1 = hn[lane + 32];
        acc0 = make_float4(v0.x * idg, v0.y * idg, v0.z * idg, v0.w * idg);
        acc1 = make_float4(v1.x * idg, v1.y * idg, v1.z * idg, v1.w * idg);
    }

    int beg = g_offs[node];
    int end = g_offs[node + 1];
    int j = beg;
    for (; j + 4 <= end; j += 4) {
        int2 e0 = g_csr[j], e1 = g_csr[j + 1], e2 = g_csr[j + 2], e3 = g_csr[j + 3];
        const float4* p0 = (const float4*)(h + (size_t)e0.x * F);
        const float4* p1 = (const float4*)(h + (size_t)e1.x * F);
        const float4* p2 = (const float4*)(h + (size_t)e2.x * F);
        const float4* p3 = (const float4*)(h + (size_t)e3.x * F);
        float4 a0 = p0[lane], b0 = p0[lane + 32];
        float4 a1 = p1[lane], b1 = p1[lane + 32];
        float4 a2 = p2[lane], b2 = p2[lane + 32];
        float4 a3 = p3[lane], b3 = p3[lane + 32];
        float c0 = __int_as_float(e0.y), c1 = __int_as_float(e1.y);
        float c2 = __int_as_float(e2.y), c3 = __int_as_float(e3.y);
        acc0.x += a0.x * c0; acc0.y += a0.y * c0; acc0.z += a0.z * c0; acc0.w += a0.w * c0;
        acc1.x += b0.x * c0; acc1.y += b0.y * c0; acc1.z += b0.z * c0; acc1.w += b0.w * c0;
        acc0.x += a1.x * c1; acc0.y += a1.y * c1; acc0.z += a1.z * c1; acc0.w += a1.w * c1;
        acc1.x += b1.x * c1; acc1.y += b1.y * c1; acc1.z += b1.z * c1; acc1.w += b1.w * c1;
        acc0.x += a2.x * c2; acc0.y += a2.y * c2; acc0.z += a2.z * c2; acc0.w += a2.w * c2;
        acc1.x += b2.x * c2; acc1.y += b2.y * c2; acc1.z += b2.z * c2; acc1.w += b2.w * c2;
        acc0.x += a3.x * c3; acc0.y += a3.y * c3; acc0.z += a3.z * c3; acc0.w += a3.w * c3;
        acc1.x += b3.x * c3; acc1.y += b3.y * c3; acc1.z += b3.z * c3; acc1.w += b3.w * c3;
    }
    for (; j < end; j++) {
        int2 e = g_csr[j];
        float cc = __int_as_float(e.y);
        const float4* hs = (const float4*)(h + (size_t)e.x * F);
        float4 a = hs[lane], b = hs[lane + 32];
        acc0.x += a.x * cc; acc0.y += a.y * cc; acc0.z += a.z * cc; acc0.w += a.w * cc;
        acc1.x += b.x * cc; acc1.y += b.y * cc; acc1.z += b.z * cc; acc1.w += b.w * cc;
    }

    #pragma unroll
    for (int t = 0; t < 2; t++) {
        float4 acc = (t == 0) ? acc0 : acc1;
        int f = (lane + 32 * t) * 4;
        float4 bb = *(const float4*)(bias + f);
        float4 w  = *(const float4*)(bnw + f);
        float4 b2 = *(const float4*)(bnb + f);
        float4 mn = *(const float4*)(bnm + f);
        float4 vr = *(const float4*)(bnv + f);
        float4 o;
        o.x = tf32r(elu1((acc.x + bb.x - mn.x) * rsqrtf(vr.x + BN_EPS) * w.x + b2.x));
        o.y = tf32r(elu1((acc.y + bb.y - mn.y) * rsqrtf(vr.y + BN_EPS) * w.y + b2.y));
        o.z = tf32r(elu1((acc.z + bb.z - mn.z) * rsqrtf(vr.z + BN_EPS) * w.z + b2.z));
        o.w = tf32r(elu1((acc.w + bb.w - mn.w) * rsqrtf(vr.w + BN_EPS) * w.w + b2.w));
        ((float4*)(out + (size_t)node * F))[lane + 32 * t] = o;
    }
}

// ===== layer 2 aggregate + BN + ELU, fused with softmax head (F=128) =====
__global__ __launch_bounds__(256)
void aggregate2_head_kernel(const float* __restrict__ bias,
                            const float* __restrict__ bnw, const float* __restrict__ bnb,
                            const float* __restrict__ bnm, const float* __restrict__ bnv,
                            const float* __restrict__ Wp, const float* __restrict__ bp,
                            float* __restrict__ out_h, float* __restrict__ out_z) {
    constexpr int F = FOUT;
    __shared__ float sW[F * NCLS];
    __shared__ float sbp[NCLS];
    for (int i = threadIdx.x; i < F * NCLS; i += blockDim.x) sW[i] = Wp[i];
    if (threadIdx.x < NCLS) sbp[threadIdx.x] = bp[threadIdx.x];
    __syncthreads();

    const float* h = (const float*)g_h2;
    int warp = (blockIdx.x * blockDim.x + threadIdx.x) >> 5;
    int lane = threadIdx.x & 31;
    if (warp >= NN) return;
    int node = warp;

    float4 acc;
    {
        float4 v = ((const float4*)(h + (size_t)node * F))[lane];
        float idg = g_invdeg[node];
        acc = make_float4(v.x * idg, v.y * idg, v.z * idg, v.w * idg);
    }

    int beg = g_offs[node];
    int end = g_offs[node + 1];
    int j = beg;
    for (; j + 4 <= end; j += 4) {
        int2 e0 = g_csr[j], e1 = g_csr[j + 1], e2 = g_csr[j + 2], e3 = g_csr[j + 3];
        float4 a0 = ((const float4*)(h + (size_t)e0.x * F))[lane];
        float4 a1 = ((const float4*)(h + (size_t)e1.x * F))[lane];
        float4 a2 = ((const float4*)(h + (size_t)e2.x * F))[lane];
        float4 a3 = ((const float4*)(h + (size_t)e3.x * F))[lane];
        float c0 = __int_as_float(e0.y), c1 = __int_as_float(e1.y);
        float c2 = __int_as_float(e2.y), c3 = __int_as_float(e3.y);
        acc.x += a0.x * c0; acc.y += a0.y * c0; acc.z += a0.z * c0; acc.w += a0.w * c0;
        acc.x += a1.x * c1; acc.y += a1.y * c1; acc.z += a1.z * c1; acc.w += a1.w * c1;
        acc.x += a2.x * c2; acc.y += a2.y * c2; acc.z += a2.z * c2; acc.w += a2.w * c2;
        acc.x += a3.x * c3; acc.y += a3.y * c3; acc.z += a3.z * c3; acc.w += a3.w * c3;
    }
    for (; j < end; j++) {
        int2 e = g_csr[j];
        float cc = __int_as_float(e.y);
        float4 v = ((const float4*)(h + (size_t)e.x * F))[lane];
        acc.x += v.x * cc; acc.y += v.y * cc; acc.z += v.z * cc; acc.w += v.w * cc;
    }

    int f = lane * 4;
    float4 bb = *(const float4*)(bias + f);
    float4 w  = *(const float4*)(bnw + f);
    float4 b2 = *(const float4*)(bnb + f);
    float4 mn = *(const float4*)(bnm + f);
    float4 vr = *(const float4*)(bnv + f);
    float4 o;
    o.x = elu1((acc.x + bb.x - mn.x) * rsqrtf(vr.x + BN_EPS) * w.x + b2.x);
    o.y = elu1((acc.y + bb.y - mn.y) * rsqrtf(vr.y + BN_EPS) * w.y + b2.y);
    o.z = elu1((acc.z + bb.z - mn.z) * rsqrtf(vr.z + BN_EPS) * w.z + b2.z);
    o.w = elu1((acc.w + bb.w - mn.w) * rsqrtf(vr.w + BN_EPS) * w.w + b2.w);
    ((float4*)(out_h + (size_t)node * F))[lane] = o;

    float p[NCLS];
    #pragma unroll
    for (int k = 0; k < NCLS; k++)
        p[k] = o.x * sW[(f + 0) * NCLS + k] + o.y * sW[(f + 1) * NCLS + k]
             + o.z * sW[(f + 2) * NCLS + k] + o.w * sW[(f + 3) * NCLS + k];
    #pragma unroll
    for (int off = 16; off > 0; off >>= 1)
        #pragma unroll
        for (int k = 0; k < NCLS; k++)
            p[k] += __shfl_xor_sync(0xffffffffu, p[k], off);

    #pragma unroll
    for (int k = 0; k < NCLS; k++) p[k] += sbp[k];
    float m = p[0];
    #pragma unroll
    for (int k = 1; k < NCLS; k++) m = fmaxf(m, p[k]);
    float ssum = 0.0f;
    #pragma unroll
    for (int k = 0; k < NCLS; k++) { p[k] = expf(p[k] - m); ssum += p[k]; }
    float inv = 1.0f / ssum;
    if (lane < NCLS) out_z[(size_t)node * NCLS + lane] = p[lane] * inv;
}

// ================= host =================
extern "C" void kernel_launch(void* const* d_in, const int* in_sizes, int n_in,
                              void* d_out, int out_size) {
    const float* x    = (const float*)d_in[0];
    const int*   ei   = (const int*)d_in[1];
    const float* W1   = (const float*)d_in[2];
    const float* b1   = (const float*)d_in[3];
    const float* bn1w = (const float*)d_in[4];
    const float* bn1b = (const float*)d_in[5];
    const float* bn1m = (const float*)d_in[6];
    const float* bn1v = (const float*)d_in[7];
    const float* W2   = (const float*)d_in[8];
    const float* b2   = (const float*)d_in[9];
    const float* bn2w = (const float*)d_in[10];
    const float* bn2b = (const float*)d_in[11];
    const float* bn2m = (const float*)d_in[12];
    const float* bn2v = (const float*)d_in[13];
    const float* Wp   = (const float*)d_in[14];
    const float* bp   = (const float*)d_in[15];

    const int* src = ei;
    const int* dst = ei + NE;

    float* out_h = (float*)d_out;
    float* out_z = out_h + (size_t)NN * FOUT;

    void *p_w1r, *p_w2r, *p_act1, *p_h1, *p_h2;
    cudaGetSymbolAddress(&p_w1r,  g_w1r);
    cudaGetSymbolAddress(&p_w2r,  g_w2r);
    cudaGetSymbolAddress(&p_act1, g_act1);
    cudaGetSymbolAddress(&p_h1,   g_h1);
    cudaGetSymbolAddress(&p_h2,   g_h2);

    constexpr int KT1 = (FIN + 15) / 16;                         // 90
    constexpr int SMEM_G = 4 * (128 * 20 + 16 * 136) * 4;        // 75776 (S=4, BLOCKN=128)

    static cudaStream_t s_side = nullptr;
    static cudaEvent_t ev_fork = nullptr, ev_join = nullptr;
    if (!s_side) {
        cudaStreamCreateWithFlags(&s_side, cudaStreamNonBlocking);
        cudaEventCreateWithFlags(&ev_fork, cudaEventDisableTiming);
        cudaEventCreateWithFlags(&ev_join, cudaEventDisableTiming);
        cudaFuncSetAttribute(mma_gemm_kernel<FHID, FIN, KT1, false, true, 4, 2>,
                             cudaFuncAttributeMaxDynamicSharedMemorySize, SMEM_G);
        cudaFuncSetAttribute(mma_gemm_kernel<FOUT, FHID, FHID / 16, true, false, 4, 2>,
                             cudaFuncAttributeMaxDynamicSharedMemorySize, SMEM_G);
    }

    const int NODE_BLKS = (NN + 255) / 256;
    const int EDGE_BLKS = (NE + 255) / 256;
    const int SCAN_BLKS = (NN + 1023) / 1024;
    const int MTILES    = (NN + 127) / 128;

    // ---- fork ----
    cudaEventRecord(ev_fork, 0);
    cudaStreamWaitEvent(s_side, ev_fork, 0);

    // same capture order as R7 so ncu samples GEMM1 again
    round_w1_kernel<<<(KPAD1 * FHID + 255) / 256, 256>>>(W1);
    zero_cnt_kernel<<<NODE_BLKS, 256, 0, s_side>>>();
    count_deg_kernel<<<EDGE_BLKS, 256, 0, s_side>>>(dst);

    mma_gemm_kernel<FHID, FIN, KT1, false, true, 4, 2>
        <<<dim3(2, MTILES), 256, SMEM_G>>>(x, (const float*)p_w1r, (float*)p_h1);

    // rest of CSR build on side stream
    scan_block_kernel<<<SCAN_BLKS, 1024, 0, s_side>>>();
    scan_bsum_kernel<<<1, 64, 0, s_side>>>(SCAN_BLKS);
    scan_add_kernel<<<SCAN_BLKS, 1024, 0, s_side>>>();
    fill_csr_kernel<<<EDGE_BLKS, 256, 0, s_side>>>(src, dst);
    round_w2_kernel<<<(FHID * FOUT + 255) / 256, 256, 0, s_side>>>(W2);
    cudaEventRecord(ev_join, s_side);

    // ---- join: aggregation needs CSR ----
    cudaStreamWaitEvent(0, ev_join, 0);

    aggregate1_kernel<<<(NN * 32) / 256, 256>>>(b1, bn1w, bn1b, bn1m, bn1v);

    mma_gemm_kernel<FOUT, FHID, FHID / 16, true, false, 4, 2>
        <<<dim3(1, MTILES), 256, SMEM_G>>>((const float*)p_act1, (const float*)p_w2r, (float*)p_h2);

    aggregate2_head_kernel<<<(NN * 32) / 256, 256>>>(b2, bn2w, bn2b, bn2m, bn2v,
                                                     Wp, bp, out_h, out_z);
}

// round 9
// speedup vs baseline: 1.0614x; 1.0614x over previous
#include <cuda_runtime.h>
#include <math.h>
#include <stdint.h>

#define NN   50000
#define NE   800000
#define FIN  1433
#define KPAD1 1440
#define FHID 256
#define FOUT 128
#define NCLS 7
#define BN_EPS 1e-5f

// ---------------- scratch (device globals; no runtime allocation) ----------------
__device__ int   g_cnt[NN];
__device__ int   g_offs[NN + 1];
__device__ int   g_cur[NN];
__device__ int   g_bsum[64];
__device__ int2  g_csr[NE];                     // (src, coef bits) packed
__device__ float g_dinv[NN];
__device__ float g_invdeg[NN];
__device__ float g_xpad[(size_t)NN * KPAD1];    // x zero-padded to K=1440, tf32-rounded
__device__ float g_w1r[(size_t)KPAD1 * FHID];   // W1 [K,N] tf32-rounded, K zero-padded
__device__ float g_w2r[(size_t)FHID * FOUT];    // W2 [K,N] tf32-rounded
__device__ float g_h1[(size_t)NN * FHID];       // x @ W1
__device__ float g_act1[(size_t)NN * FHID];     // ELU(BN(agg1)), tf32-rounded
__device__ float g_h2[(size_t)NN * FOUT];       // act1 @ W2

// ================= helpers =================
__device__ __forceinline__ uint32_t smem_u32(const void* p) {
    uint32_t a;
    asm("{ .reg .u64 t; cvta.to.shared.u64 t, %1; cvt.u32.u64 %0, t; }" : "=r"(a) : "l"(p));
    return a;
}

__device__ __forceinline__ float tf32r(float x) {
    uint32_t u;
    asm("cvt.rna.tf32.f32 %0, %1;" : "=r"(u) : "f"(x));
    return __uint_as_float(u);
}

__device__ __forceinline__ void cp16(uint32_t dst, const void* src, int srcsize) {
    asm volatile("cp.async.cg.shared.global [%0], [%1], 16, %2;"
                 :: "r"(dst), "l"(src), "r"(srcsize) : "memory");
}

__device__ __forceinline__ void mma_tf32(float* c, const uint32_t* a, const uint32_t* b) {
    asm volatile(
        "mma.sync.aligned.m16n8k8.row.col.f32.tf32.tf32.f32 "
        "{%0,%1,%2,%3}, {%4,%5,%6,%7}, {%8,%9}, {%0,%1,%2,%3};"
        : "+f"(c[0]), "+f"(c[1]), "+f"(c[2]), "+f"(c[3])
        : "r"(a[0]), "r"(a[1]), "r"(a[2]), "r"(a[3]), "r"(b[0]), "r"(b[1]));
}

// ================= preprocessing =================
// pad + tf32-round x: one float4 of output per thread
__global__ __launch_bounds__(256)
void pad_x_kernel(const float* __restrict__ x) {
    long idx4 = (long)blockIdx.x * blockDim.x + threadIdx.x;
    if (idx4 >= (long)NN * (KPAD1 / 4)) return;
    int row = (int)(idx4 / (KPAD1 / 4));
    int col = (int)(idx4 - (long)row * (KPAD1 / 4)) * 4;
    const float* xr = x + (size_t)row * FIN;
    float4 o;
    o.x = (col + 0 < FIN) ? tf32r(xr[col + 0]) : 0.0f;
    o.y = (col + 1 < FIN) ? tf32r(xr[col + 1]) : 0.0f;
    o.z = (col + 2 < FIN) ? tf32r(xr[col + 2]) : 0.0f;
    o.w = (col + 3 < FIN) ? tf32r(xr[col + 3]) : 0.0f;
    *(float4*)(g_xpad + (size_t)row * KPAD1 + col) = o;
}

__global__ void round_w1_kernel(const float* __restrict__ W1) {
    int idx = blockIdx.x * blockDim.x + threadIdx.x;
    if (idx >= KPAD1 * FHID) return;
    int k = idx / FHID;
    g_w1r[idx] = (k < FIN) ? tf32r(W1[idx]) : 0.0f;
}

__global__ void round_w2_kernel(const float* __restrict__ W2) {
    int idx = blockIdx.x * blockDim.x + threadIdx.x;
    if (idx >= FHID * FOUT) return;
    g_w2r[idx] = tf32r(W2[idx]);
}

// ================= CSR build =================
__global__ void zero_cnt_kernel() {
    int i = blockIdx.x * blockDim.x + threadIdx.x;
    if (i < NN) g_cnt[i] = 0;
}

__global__ void count_deg_kernel(const int* __restrict__ dst) {
    int e = blockIdx.x * blockDim.x + threadIdx.x;
    if (e < NE) atomicAdd(&g_cnt[dst[e]], 1);
}

__global__ __launch_bounds__(1024)
void scan_block_kernel() {
    __shared__ int ws[32];
    int t = threadIdx.x, b = blockIdx.x;
    int i = b * 1024 + t;
    int v = (i < NN) ? g_cnt[i] : 0;
    if (i < NN) {
        float d = (float)v + 1.0f;
        g_dinv[i]   = rsqrtf(d);
        g_invdeg[i] = 1.0f / d;
    }
    int lane = t & 31, w = t >> 5;
    int x = v;
    #pragma unroll
    for (int o = 1; o < 32; o <<= 1) {
        int y = __shfl_up_sync(0xffffffffu, x, o);
        if (lane >= o) x += y;
    }
    if (lane == 31) ws[w] = x;
    __syncthreads();
    if (w == 0) {
        int s = ws[lane];
        #pragma unroll
        for (int o = 1; o < 32; o <<= 1) {
            int y = __shfl_up_sync(0xffffffffu, s, o);
            if (lane >= o) s += y;
        }
        ws[lane] = s;
    }
    __syncthreads();
    int pre = (w > 0) ? ws[w - 1] : 0;
    if (i < NN) g_offs[i] = pre + x - v;
    if (t == 1023) g_bsum[b] = pre + x;
}

__global__ void scan_bsum_kernel(int nblk) {
    __shared__ int s[64];
    int t = threadIdx.x;
    s[t] = (t < nblk) ? g_bsum[t] : 0;
    __syncthreads();
    if (t == 0) {
        int acc = 0;
        for (int i = 0; i < nblk; i++) { int v = s[i]; s[i] = acc; acc += v; }
    }
    __syncthreads();
    if (t < nblk) g_bsum[t] = s[t];
}

__global__ __launch_bounds__(1024)
void scan_add_kernel() {
    int t = threadIdx.x, b = blockIdx.x;
    int i = b * 1024 + t;
    if (i < NN) {
        int o = g_offs[i] + g_bsum[b];
        g_offs[i] = o;
        g_cur[i]  = o;
    }
    if (i == 0) g_offs[NN] = NE;
}

__global__ void fill_csr_kernel(const int* __restrict__ src, const int* __restrict__ dst) {
    int e = blockIdx.x * blockDim.x + threadIdx.x;
    if (e < NE) {
        int s = src[e];
        int d = dst[e];
        int p = atomicAdd(&g_cur[d], 1);
        g_csr[p] = make_int2(s, __float_as_int(g_dinv[s] * g_dinv[d]));
    }
}

// ================= tf32 mma.sync GEMM (all inputs pre-rounded, 16B-aligned) =================
// C[M, NMAT] = A[M, KA] @ B[KA, NMAT]. Block 128 x (WN*64); WM x WN warps;
// warp tile (128/WM) x 64. m16n8k8 tf32 mma, S=4 cp.async pipeline, 2 CTAs/SM.
template <int NMAT, int KA, int KTILES, int WM, int WN>
__global__ __launch_bounds__(WM * WN * 32, 2)
void mma_gemm_kernel(const float* __restrict__ A, const float* __restrict__ B,
                     float* __restrict__ C) {
    constexpr int S = 4;
    constexpr int THREADS = WM * WN * 32;
    constexpr int BLOCKN = WN * 64;
    constexpr int MT = 128 / WM / 16;
    constexpr int AS_STRIDE = 20;
    constexpr int BS_STRIDE = BLOCKN + 8;
    constexpr int A_FLOATS = 128 * AS_STRIDE;
    constexpr int B_FLOATS = 16 * BS_STRIDE;
    constexpr int STG = A_FLOATS + B_FLOATS;
    constexpr int FA = 2048 / THREADS;
    constexpr int FB = 16 * BLOCKN / THREADS;

    extern __shared__ float sm[];
    uint32_t smb = smem_u32(sm);

    int tid  = threadIdx.x;
    int lane = tid & 31;
    int w    = tid >> 5;
    int g    = lane >> 2;
    int tig  = lane & 3;
    int wm   = (w % WM) * (16 * MT);
    int wn   = (w / WM) * 64;
    int m0   = blockIdx.y * 128;
    int n0   = blockIdx.x * BLOCKN;

    int a_row  = tid / (16 / FA);
    int a_off  = (tid % (16 / FA)) * FA;
    int a_m    = m0 + a_row;
    bool a_ok  = (a_m < NN);
    const float* Ag = A + (size_t)(a_ok ? a_m : 0) * KA;
    uint32_t a_dst0 = smb + (uint32_t)(a_row * AS_STRIDE + a_off) * 4;

    constexpr int B_TPR = BLOCKN / FB;
    int b_row = tid / B_TPR;
    int b_col = (tid % B_TPR) * FB;
    const float* Bg = B + (size_t)b_row * NMAT + n0 + b_col;
    uint32_t b_dst0 = smb + (uint32_t)(A_FLOATS + b_row * BS_STRIDE + b_col) * 4;

    float c[MT][8][4];
    #pragma unroll
    for (int mt = 0; mt < MT; mt++)
        #pragma unroll
        for (int nt = 0; nt < 8; nt++)
            #pragma unroll
            for (int q = 0; q < 4; q++) c[mt][nt][q] = 0.0f;

    auto load_a = [&](int kt, uint32_t off) {
        const float* ga = Ag + kt * 16 + a_off;
        int sz = a_ok ? 16 : 0;
        cp16(a_dst0 + off, ga, sz);
        if (FA == 8) cp16(a_dst0 + off + 16, ga + 4, sz);
    };
    auto load_b = [&](int kt, uint32_t off) {
        const float* gb = Bg + (size_t)(kt * 16) * NMAT;
        #pragma unroll
        for (int i = 0; i < FB / 4; i++)
            cp16(b_dst0 + off + i * 16, gb + i * 4, 16);
    };

    #pragma unroll
    for (int s = 0; s < S - 1; s++) {
        uint32_t off = (uint32_t)(s * STG) * 4;
        if (s < KTILES) { load_a(s, off); load_b(s, off); }
        asm volatile("cp.async.commit_group;" ::: "memory");
    }

    for (int kt = 0; kt < KTILES; kt++) {
        asm volatile("cp.async.wait_group %0;" :: "n"(S - 2) : "memory");
        __syncthreads();

        {
            int nk = kt + S - 1;
            if (nk < KTILES) {
                uint32_t off = (uint32_t)((nk % S) * STG) * 4;
                load_a(nk, off);
                load_b(nk, off);
            }
            asm volatile("cp.async.commit_group;" ::: "memory");
        }

        const float* As = sm + (kt % S) * STG;
        const float* Bs = As + A_FLOATS;

        #pragma unroll
        for (int kk = 0; kk < 16; kk += 8) {
            uint32_t a[MT][4], b[8][2];
            #pragma unroll
            for (int mt = 0; mt < MT; mt++) {
                int r = wm + mt * 16 + g;
                a[mt][0] = __float_as_uint(As[r * AS_STRIDE + kk + tig]);
                a[mt][1] = __float_as_uint(As[(r + 8) * AS_STRIDE + kk + tig]);
                a[mt][2] = __float_as_uint(As[r * AS_STRIDE + kk + tig + 4]);
                a[mt][3] = __float_as_uint(As[(r + 8) * AS_STRIDE + kk + tig + 4]);
            }
            #pragma unroll
            for (int nt = 0; nt < 8; nt++) {
                int ccol = wn + nt * 8 + g;
                b[nt][0] = __float_as_uint(Bs[(kk + tig) * BS_STRIDE + ccol]);
                b[nt][1] = __float_as_uint(Bs[(kk + tig + 4) * BS_STRIDE + ccol]);
            }
            #pragma unroll
            for (int mt = 0; mt < MT; mt++)
                #pragma unroll
                for (int nt = 0; nt < 8; nt++)
                    mma_tf32(c[mt][nt], a[mt], b[nt]);
        }
    }

    #pragma unroll
    for (int mt = 0; mt < MT; mt++) {
        int r0 = m0 + wm + mt * 16 + g;
        #pragma unroll
        for (int nt = 0; nt < 8; nt++) {
            int col = n0 + wn + nt * 8 + 2 * tig;
            if (r0 < NN)
                *(float2*)(C + (size_t)r0 * NMAT + col) = make_float2(c[mt][nt][0], c[mt][nt][1]);
            if (r0 + 8 < NN)
                *(float2*)(C + (size_t)(r0 + 8) * NMAT + col) = make_float2(c[mt][nt][2], c[mt][nt][3]);
        }
    }
}

// ================= fused aggregate + bias + BN + ELU (layer 1, F=256) =================
__device__ __forceinline__ float elu1(float x) { return x > 0.0f ? x : expm1f(x); }

__global__ __launch_bounds__(256)
void aggregate1_kernel(const float* __restrict__ bias,
                       const float* __restrict__ bnw, const float* __restrict__ bnb,
                       const float* __restrict__ bnm, const float* __restrict__ bnv) {
    const float* h = (const float*)g_h1;
    float* out = (float*)g_act1;
    constexpr int F = FHID;

    int warp = (blockIdx.x * blockDim.x + threadIdx.x) >> 5;
    int lane = threadIdx.x & 31;
    if (warp >= NN) return;
    int node = warp;

    float4 acc0, acc1;
    {
        const float4* hn = (const float4*)(h + (size_t)node * F);
        float idg = g_invdeg[node];
        float4 v0 = hn[lane], v1 = hn[lane + 32];
        acc0 = make_float4(v0.x * idg, v0.y * idg, v0.z * idg, v0.w * idg);
        acc1 = make_float4(v1.x * idg, v1.y * idg, v1.z * idg, v1.w * idg);
    }

    int beg = g_offs[node];
    int end = g_offs[node + 1];
    int j = beg;
    for (; j + 4 <= end; j += 4) {
        int2 e0 = g_csr[j], e1 = g_csr[j + 1], e2 = g_csr[j + 2], e3 = g_csr[j + 3];
        const float4* p0 = (const float4*)(h + (size_t)e0.x * F);
        const float4* p1 = (const float4*)(h + (size_t)e1.x * F);
        const float4* p2 = (const float4*)(h + (size_t)e2.x * F);
        const float4* p3 = (const float4*)(h + (size_t)e3.x * F);
        float4 a0 = p0[lane], b0 = p0[lane + 32];
        float4 a1 = p1[lane], b1 = p1[lane + 32];
        float4 a2 = p2[lane], b2 = p2[lane + 32];
        float4 a3 = p3[lane], b3 = p3[lane + 32];
        float c0 = __int_as_float(e0.y), c1 = __int_as_float(e1.y);
        float c2 = __int_as_float(e2.y), c3 = __int_as_float(e3.y);
        acc0.x += a0.x * c0; acc0.y += a0.y * c0; acc0.z += a0.z * c0; acc0.w += a0.w * c0;
        acc1.x += b0.x * c0; acc1.y += b0.y * c0; acc1.z += b0.z * c0; acc1.w += b0.w * c0;
        acc0.x += a1.x * c1; acc0.y += a1.y * c1; acc0.z += a1.z * c1; acc0.w += a1.w * c1;
        acc1.x += b1.x * c1; acc1.y += b1.y * c1; acc1.z += b1.z * c1; acc1.w += b1.w * c1;
        acc0.x += a2.x * c2; acc0.y += a2.y * c2; acc0.z += a2.z * c2; acc0.w += a2.w * c2;
        acc1.x += b2.x * c2; acc1.y += b2.y * c2; acc1.z += b2.z * c2; acc1.w += b2.w * c2;
        acc0.x += a3.x * c3; acc0.y += a3.y * c3; acc0.z += a3.z * c3; acc0.w += a3.w * c3;
        acc1.x += b3.x * c3; acc1.y += b3.y * c3; acc1.z += b3.z * c3; acc1.w += b3.w * c3;
    }
    for (; j < end; j++) {
        int2 e = g_csr[j];
        float cc = __int_as_float(e.y);
        const float4* hs = (const float4*)(h + (size_t)e.x * F);
        float4 a = hs[lane], b = hs[lane + 32];
        acc0.x += a.x * cc; acc0.y += a.y * cc; acc0.z += a.z * cc; acc0.w += a.w * cc;
        acc1.x += b.x * cc; acc1.y += b.y * cc; acc1.z += b.z * cc; acc1.w += b.w * cc;
    }

    #pragma unroll
    for (int t = 0; t < 2; t++) {
        float4 acc = (t == 0) ? acc0 : acc1;
        int f = (lane + 32 * t) * 4;
        float4 bb = *(const float4*)(bias + f);
        float4 w  = *(const float4*)(bnw + f);
        float4 b2 = *(const float4*)(bnb + f);
        float4 mn = *(const float4*)(bnm + f);
        float4 vr = *(const float4*)(bnv + f);
        float4 o;
        o.x = tf32r(elu1((acc.x + bb.x - mn.x) * rsqrtf(vr.x + BN_EPS) * w.x + b2.x));
        o.y = tf32r(elu1((acc.y + bb.y - mn.y) * rsqrtf(vr.y + BN_EPS) * w.y + b2.y));
        o.z = tf32r(elu1((acc.z + bb.z - mn.z) * rsqrtf(vr.z + BN_EPS) * w.z + b2.z));
        o.w = tf32r(elu1((acc.w + bb.w - mn.w) * rsqrtf(vr.w + BN_EPS) * w.w + b2.w));
        ((float4*)(out + (size_t)node * F))[lane + 32 * t] = o;
    }
}

// ===== layer 2 aggregate + BN + ELU, fused with softmax head (F=128) =====
__global__ __launch_bounds__(256)
void aggregate2_head_kernel(const float* __restrict__ bias,
                            const float* __restrict__ bnw, const float* __restrict__ bnb,
                            const float* __restrict__ bnm, const float* __restrict__ bnv,
                            const float* __restrict__ Wp, const float* __restrict__ bp,
                            float* __restrict__ out_h, float* __restrict__ out_z) {
    constexpr int F = FOUT;
    __shared__ float sW[F * NCLS];
    __shared__ float sbp[NCLS];
    for (int i = threadIdx.x; i < F * NCLS; i += blockDim.x) sW[i] = Wp[i];
    if (threadIdx.x < NCLS) sbp[threadIdx.x] = bp[threadIdx.x];
    __syncthreads();

    const float* h = (const float*)g_h2;
    int warp = (blockIdx.x * blockDim.x + threadIdx.x) >> 5;
    int lane = threadIdx.x & 31;
    if (warp >= NN) return;
    int node = warp;

    float4 acc;
    {
        float4 v = ((const float4*)(h + (size_t)node * F))[lane];
        float idg = g_invdeg[node];
        acc = make_float4(v.x * idg, v.y * idg, v.z * idg, v.w * idg);
    }

    int beg = g_offs[node];
    int end = g_offs[node + 1];
    int j = beg;
    for (; j + 4 <= end; j += 4) {
        int2 e0 = g_csr[j], e1 = g_csr[j + 1], e2 = g_csr[j + 2], e3 = g_csr[j + 3];
        float4 a0 = ((const float4*)(h + (size_t)e0.x * F))[lane];
        float4 a1 = ((const float4*)(h + (size_t)e1.x * F))[lane];
        float4 a2 = ((const float4*)(h + (size_t)e2.x * F))[lane];
        float4 a3 = ((const float4*)(h + (size_t)e3.x * F))[lane];
        float c0 = __int_as_float(e0.y), c1 = __int_as_float(e1.y);
        float c2 = __int_as_float(e2.y), c3 = __int_as_float(e3.y);
        acc.x += a0.x * c0; acc.y += a0.y * c0; acc.z += a0.z * c0; acc.w += a0.w * c0;
        acc.x += a1.x * c1; acc.y += a1.y * c1; acc.z += a1.z * c1; acc.w += a1.w * c1;
        acc.x += a2.x * c2; acc.y += a2.y * c2; acc.z += a2.z * c2; acc.w += a2.w * c2;
        acc.x += a3.x * c3; acc.y += a3.y * c3; acc.z += a3.z * c3; acc.w += a3.w * c3;
    }
    for (; j < end; j++) {
        int2 e = g_csr[j];
        float cc = __int_as_float(e.y);
        float4 v = ((const float4*)(h + (size_t)e.x * F))[lane];
        acc.x += v.x * cc; acc.y += v.y * cc; acc.z += v.z * cc; acc.w += v.w * cc;
    }

    int f = lane * 4;
    float4 bb = *(const float4*)(bias + f);
    float4 w  = *(const float4*)(bnw + f);
    float4 b2 = *(const float4*)(bnb + f);
    float4 mn = *(const float4*)(bnm + f);
    float4 vr = *(const float4*)(bnv + f);
    float4 o;
    o.x = elu1((acc.x + bb.x - mn.x) * rsqrtf(vr.x + BN_EPS) * w.x + b2.x);
    o.y = elu1((acc.y + bb.y - mn.y) * rsqrtf(vr.y + BN_EPS) * w.y + b2.y);
    o.z = elu1((acc.z + bb.z - mn.z) * rsqrtf(vr.z + BN_EPS) * w.z + b2.z);
    o.w = elu1((acc.w + bb.w - mn.w) * rsqrtf(vr.w + BN_EPS) * w.w + b2.w);
    ((float4*)(out_h + (size_t)node * F))[lane] = o;

    float p[NCLS];
    #pragma unroll
    for (int k = 0; k < NCLS; k++)
        p[k] = o.x * sW[(f + 0) * NCLS + k] + o.y * sW[(f + 1) * NCLS + k]
             + o.z * sW[(f + 2) * NCLS + k] + o.w * sW[(f + 3) * NCLS + k];
    #pragma unroll
    for (int off = 16; off > 0; off >>= 1)
        #pragma unroll
        for (int k = 0; k < NCLS; k++)
            p[k] += __shfl_xor_sync(0xffffffffu, p[k], off);

    #pragma unroll
    for (int k = 0; k < NCLS; k++) p[k] += sbp[k];
    float m = p[0];
    #pragma unroll
    for (int k = 1; k < NCLS; k++) m = fmaxf(m, p[k]);
    float ssum = 0.0f;
    #pragma unroll
    for (int k = 0; k < NCLS; k++) { p[k] = expf(p[k] - m); ssum += p[k]; }
    float inv = 1.0f / ssum;
    if (lane < NCLS) out_z[(size_t)node * NCLS + lane] = p[lane] * inv;
}

// ================= host =================
extern "C" void kernel_launch(void* const* d_in, const int* in_sizes, int n_in,
                              void* d_out, int out_size) {
    const float* x    = (const float*)d_in[0];
    const int*   ei   = (const int*)d_in[1];
    const float* W1   = (const float*)d_in[2];
    const float* b1   = (const float*)d_in[3];
    const float* bn1w = (const float*)d_in[4];
    const float* bn1b = (const float*)d_in[5];
    const float* bn1m = (const float*)d_in[6];
    const float* bn1v = (const float*)d_in[7];
    const float* W2   = (const float*)d_in[8];
    const float* b2   = (const float*)d_in[9];
    const float* bn2w = (const float*)d_in[10];
    const float* bn2b = (const float*)d_in[11];
    const float* bn2m = (const float*)d_in[12];
    const float* bn2v = (const float*)d_in[13];
    const float* Wp   = (const float*)d_in[14];
    const float* bp   = (const float*)d_in[15];

    const int* src = ei;
    const int* dst = ei + NE;

    float* out_h = (float*)d_out;
    float* out_z = out_h + (size_t)NN * FOUT;

    void *p_xpad, *p_w1r, *p_w2r, *p_act1, *p_h1, *p_h2;
    cudaGetSymbolAddress(&p_xpad, g_xpad);
    cudaGetSymbolAddress(&p_w1r,  g_w1r);
    cudaGetSymbolAddress(&p_w2r,  g_w2r);
    cudaGetSymbolAddress(&p_act1, g_act1);
    cudaGetSymbolAddress(&p_h1,   g_h1);
    cudaGetSymbolAddress(&p_h2,   g_h2);

    constexpr int SMEM_G = 4 * (128 * 20 + 16 * 136) * 4;        // 75776 (S=4, BLOCKN=128)

    static cudaStream_t s_side = nullptr;
    static cudaEvent_t ev_fork = nullptr, ev_join = nullptr;
    if (!s_side) {
        cudaStreamCreateWithFlags(&s_side, cudaStreamNonBlocking);
        cudaEventCreateWithFlags(&ev_fork, cudaEventDisableTiming);
        cudaEventCreateWithFlags(&ev_join, cudaEventDisableTiming);
        cudaFuncSetAttribute(mma_gemm_kernel<FHID, KPAD1, KPAD1 / 16, 4, 2>,
                             cudaFuncAttributeMaxDynamicSharedMemorySize, SMEM_G);
        cudaFuncSetAttribute(mma_gemm_kernel<FOUT, FHID, FHID / 16, 4, 2>,
                             cudaFuncAttributeMaxDynamicSharedMemorySize, SMEM_G);
    }

    const int NODE_BLKS = (NN + 255) / 256;
    const int EDGE_BLKS = (NE + 255) / 256;
    const int SCAN_BLKS = (NN + 1023) / 1024;
    const int MTILES    = (NN + 127) / 128;
    const long XPAD4    = (long)NN * (KPAD1 / 4);

    // ---- fork ----
    cudaEventRecord(ev_fork, 0);
    cudaStreamWaitEvent(s_side, ev_fork, 0);

    // enqueue order keeps GEMM1 as 4th launch (ncu sample slot):
    // #0 pad_x (main), #1 round_w1 (main), #2 zero (side), #3 GEMM1 (main)
    pad_x_kernel<<<(unsigned)((XPAD4 + 255) / 256), 256>>>(x);
    round_w1_kernel<<<(KPAD1 * FHID + 255) / 256, 256>>>(W1);
    zero_cnt_kernel<<<NODE_BLKS, 256, 0, s_side>>>();

    mma_gemm_kernel<FHID, KPAD1, KPAD1 / 16, 4, 2>
        <<<dim3(2, MTILES), 256, SMEM_G>>>((const float*)p_xpad, (const float*)p_w1r, (float*)p_h1);

    // rest of CSR build on side stream
    count_deg_kernel<<<EDGE_BLKS, 256, 0, s_side>>>(dst);
    scan_block_kernel<<<SCAN_BLKS, 1024, 0, s_side>>>();
    scan_bsum_kernel<<<1, 64, 0, s_side>>>(SCAN_BLKS);
    scan_add_kernel<<<SCAN_BLKS, 1024, 0, s_side>>>();
    fill_csr_kernel<<<EDGE_BLKS, 256, 0, s_side>>>(src, dst);
    round_w2_kernel<<<(FHID * FOUT + 255) / 256, 256, 0, s_side>>>(W2);
    cudaEventRecord(ev_join, s_side);

    // ---- join: aggregation needs CSR ----
    cudaStreamWaitEvent(0, ev_join, 0);

    aggregate1_kernel<<<(NN * 32) / 256, 256>>>(b1, bn1w, bn1b, bn1m, bn1v);

    mma_gemm_kernel<FOUT, FHID, FHID / 16, 4, 2>
        <<<dim3(1, MTILES), 256, SMEM_G>>>((const float*)p_act1, (const float*)p_w2r, (float*)p_h2);

    aggregate2_head_kernel<<<(NN * 32) / 256, 256>>>(b2, bn2w, bn2b, bn2m, bn2v,
                                                     Wp, bp, out_h, out_z);
}

// round 10
// speedup vs baseline: 1.6365x; 1.5418x over previous
#include <cuda_runtime.h>
#include <cuda_fp16.h>
#include <math.h>
#include <stdint.h>

#define NN   50000
#define NE   800000
#define FIN  1433
#define KPAD1 1440
#define KT1  90            // KPAD1/16
#define NRB  3125          // NN/16 row-blocks (exact)
#define FHID 256
#define FOUT 128
#define NCLS 7
#define BN_EPS 1e-5f

// ---------------- scratch (device globals; no runtime allocation) ----------------
__device__ int   g_cnt[NN];
__device__ int   g_offs[NN + 1];
__device__ int   g_cur[NN];
__device__ int   g_bsum[64];
__device__ int2  g_csr[NE];
__device__ float g_dinv[NN];
__device__ float g_invdeg[NN];
// x as fp16 in mma-fragment-permuted tiles: tile (rb, kt) = 16 rows x 16 k = 512B,
// tile index rb*KT1+kt, within tile: lane*16B = {A[r0+g][k0..k0+1], A[r0+g+8][k0..],
// A[r0+g][k0+8..], A[r0+g+8][k0+8..]} as half2 x4 (r0=rb*16, k0=kt*16+2*tig)
__device__ __half2 g_xh[(size_t)NRB * KT1 * 128];
// W1 as fp16, kp-pair interleaved: g_w1h[kp*256+n] = {W1[2kp][n], W1[2kp+1][n]}
__device__ __half2 g_w1h[(KPAD1 / 2) * FHID];
__device__ float g_w2r[(size_t)FHID * FOUT];
__device__ float g_h1[(size_t)NN * FHID];
__device__ float g_act1[(size_t)NN * FHID];
__device__ float g_h2[(size_t)NN * FOUT];

// ================= helpers =================
__device__ __forceinline__ uint32_t smem_u32(const void* p) {
    uint32_t a;
    asm("{ .reg .u64 t; cvta.to.shared.u64 t, %1; cvt.u32.u64 %0, t; }" : "=r"(a) : "l"(p));
    return a;
}

__device__ __forceinline__ float tf32r(float x) {
    uint32_t u;
    asm("cvt.rna.tf32.f32 %0, %1;" : "=r"(u) : "f"(x));
    return __uint_as_float(u);
}

__device__ __forceinline__ void cp16(uint32_t dst, const void* src, int srcsize) {
    asm volatile("cp.async.cg.shared.global [%0], [%1], 16, %2;"
                 :: "r"(dst), "l"(src), "r"(srcsize) : "memory");
}

__device__ __forceinline__ void mma_f16(float* c, const uint32_t* a, const uint32_t* b) {
    asm volatile(
        "mma.sync.aligned.m16n8k16.row.col.f32.f16.f16.f32 "
        "{%0,%1,%2,%3}, {%4,%5,%6,%7}, {%8,%9}, {%0,%1,%2,%3};"
        : "+f"(c[0]), "+f"(c[1]), "+f"(c[2]), "+f"(c[3])
        : "r"(a[0]), "r"(a[1]), "r"(a[2]), "r"(a[3]), "r"(b[0]), "r"(b[1]));
}

__device__ __forceinline__ void mma_tf32(float* c, const uint32_t* a, const uint32_t* b) {
    asm volatile(
        "mma.sync.aligned.m16n8k8.row.col.f32.tf32.tf32.f32 "
        "{%0,%1,%2,%3}, {%4,%5,%6,%7}, {%8,%9}, {%0,%1,%2,%3};"
        : "+f"(c[0]), "+f"(c[1]), "+f"(c[2]), "+f"(c[3])
        : "r"(a[0]), "r"(a[1]), "r"(a[2]), "r"(a[3]), "r"(b[0]), "r"(b[1]));
}

// ================= preprocessing =================
// x -> fp16 fragment-permuted tiles
__global__ __launch_bounds__(256)
void pad_xh_kernel(const float* __restrict__ x) {
    int idx = blockIdx.x * blockDim.x + threadIdx.x;
    if (idx >= NRB * KT1 * 32) return;
    int lane = idx & 31;
    int tile = idx >> 5;
    int kt = tile % KT1;
    int rb = tile / KT1;
    int g = lane >> 2, tig = lane & 3;
    int row0 = rb * 16 + g;
    int k0 = kt * 16 + 2 * tig;
    const float* xr0 = x + (size_t)row0 * FIN;
    const float* xr1 = xr0 + (size_t)8 * FIN;

    float a0 = (k0     < FIN) ? xr0[k0]     : 0.0f;
    float a1 = (k0 + 1 < FIN) ? xr0[k0 + 1] : 0.0f;
    float b0 = (k0     < FIN) ? xr1[k0]     : 0.0f;
    float b1 = (k0 + 1 < FIN) ? xr1[k0 + 1] : 0.0f;
    int k8 = k0 + 8;
    float a2 = (k8     < FIN) ? xr0[k8]     : 0.0f;
    float a3 = (k8 + 1 < FIN) ? xr0[k8 + 1] : 0.0f;
    float b2 = (k8     < FIN) ? xr1[k8]     : 0.0f;
    float b3 = (k8 + 1 < FIN) ? xr1[k8 + 1] : 0.0f;

    __half2* dst = g_xh + (size_t)tile * 128 + lane * 4;
    dst[0] = __floats2half2_rn(a0, a1);
    dst[1] = __floats2half2_rn(b0, b1);
    dst[2] = __floats2half2_rn(a2, a3);
    dst[3] = __floats2half2_rn(b2, b3);
}

__global__ void round_w1h_kernel(const float* __restrict__ W1) {
    int idx = blockIdx.x * blockDim.x + threadIdx.x;
    if (idx >= (KPAD1 / 2) * FHID) return;
    int kp = idx >> 8;
    int n = idx & 255;
    int k0 = 2 * kp;
    float lo = (k0     < FIN) ? W1[(size_t)k0 * FHID + n]       : 0.0f;
    float hi = (k0 + 1 < FIN) ? W1[(size_t)(k0 + 1) * FHID + n] : 0.0f;
    g_w1h[idx] = __floats2half2_rn(lo, hi);
}

__global__ void round_w2_kernel(const float* __restrict__ W2) {
    int idx = blockIdx.x * blockDim.x + threadIdx.x;
    if (idx >= FHID * FOUT) return;
    g_w2r[idx] = tf32r(W2[idx]);
}

// ================= CSR build =================
__global__ void zero_cnt_kernel() {
    int i = blockIdx.x * blockDim.x + threadIdx.x;
    if (i < NN) g_cnt[i] = 0;
}

__global__ void count_deg_kernel(const int* __restrict__ dst) {
    int e = blockIdx.x * blockDim.x + threadIdx.x;
    if (e < NE) atomicAdd(&g_cnt[dst[e]], 1);
}

__global__ __launch_bounds__(1024)
void scan_block_kernel() {
    __shared__ int ws[32];
    int t = threadIdx.x, b = blockIdx.x;
    int i = b * 1024 + t;
    int v = (i < NN) ? g_cnt[i] : 0;
    if (i < NN) {
        float d = (float)v + 1.0f;
        g_dinv[i]   = rsqrtf(d);
        g_invdeg[i] = 1.0f / d;
    }
    int lane = t & 31, w = t >> 5;
    int x = v;
    #pragma unroll
    for (int o = 1; o < 32; o <<= 1) {
        int y = __shfl_up_sync(0xffffffffu, x, o);
        if (lane >= o) x += y;
    }
    if (lane == 31) ws[w] = x;
    __syncthreads();
    if (w == 0) {
        int s = ws[lane];
        #pragma unroll
        for (int o = 1; o < 32; o <<= 1) {
            int y = __shfl_up_sync(0xffffffffu, s, o);
            if (lane >= o) s += y;
        }
        ws[lane] = s;
    }
    __syncthreads();
    int pre = (w > 0) ? ws[w - 1] : 0;
    if (i < NN) g_offs[i] = pre + x - v;
    if (t == 1023) g_bsum[b] = pre + x;
}

__global__ void scan_bsum_kernel(int nblk) {
    __shared__ int s[64];
    int t = threadIdx.x;
    s[t] = (t < nblk) ? g_bsum[t] : 0;
    __syncthreads();
    if (t == 0) {
        int acc = 0;
        for (int i = 0; i < nblk; i++) { int v = s[i]; s[i] = acc; acc += v; }
    }
    __syncthreads();
    if (t < nblk) g_bsum[t] = s[t];
}

__global__ __launch_bounds__(1024)
void scan_add_kernel() {
    int t = threadIdx.x, b = blockIdx.x;
    int i = b * 1024 + t;
    if (i < NN) {
        int o = g_offs[i] + g_bsum[b];
        g_offs[i] = o;
        g_cur[i]  = o;
    }
    if (i == 0) g_offs[NN] = NE;
}

__global__ void fill_csr_kernel(const int* __restrict__ src, const int* __restrict__ dst) {
    int e = blockIdx.x * blockDim.x + threadIdx.x;
    if (e < NE) {
        int s = src[e];
        int d = dst[e];
        int p = atomicAdd(&g_cur[d], 1);
        g_csr[p] = make_int2(s, __float_as_int(g_dinv[s] * g_dinv[d]));
    }
}

// ================= GEMM1: fp16 m16n8k16, fragment-permuted A =================
// h1[NN,256] = xh @ w1h. Block 128x128 (grid 2 x 391), 8 warps (4 M x 2 N),
// warp tile 32x64. S=6 cp.async stages, 2 CTAs/SM.
__global__ __launch_bounds__(256, 2)
void gemm1_fp16_kernel(float* __restrict__ C) {
    constexpr int S = 6;
    constexpr int A_BYTES = 4096;           // 8 tiles x 512B
    constexpr int B_BYTES = 8 * 544;        // 8 kp-rows x (128 half2 + pad)
    constexpr int STG_B = A_BYTES + B_BYTES;

    extern __shared__ char sm[];
    uint32_t smb = smem_u32(sm);

    int tid = threadIdx.x, lane = tid & 31, w = tid >> 5;
    int g = lane >> 2, tig = lane & 3;
    int wm = (w & 3) * 32;
    int wn = (w >> 2) * 64;
    int m0 = blockIdx.y * 128;
    int n0 = blockIdx.x * 128;

    // A: thread loads one 16B chunk of tile (tid>>5) per stage
    int a_tl = tid >> 5;
    int a_rb = (m0 >> 4) + a_tl;
    bool a_ok = (a_rb < NRB);
    int a_rbs = a_ok ? a_rb : 0;
    uint32_t a_dst0 = smb + (uint32_t)(a_tl * 512 + (tid & 31) * 16);

    // B: thread loads one 16B chunk (4 half2) of kp-row (tid>>5)
    int b_row = tid >> 5;
    int b_chunk = tid & 31;
    uint32_t b_dst0 = smb + (uint32_t)(A_BYTES + b_row * 544 + b_chunk * 16);

    float c[2][8][4];
    #pragma unroll
    for (int mt = 0; mt < 2; mt++)
        #pragma unroll
        for (int nt = 0; nt < 8; nt++)
            #pragma unroll
            for (int q = 0; q < 4; q++) c[mt][nt][q] = 0.0f;

    auto load_stage = [&](int kt, int slot) {
        uint32_t off = (uint32_t)(slot * STG_B);
        const char* asrc = (const char*)g_xh + ((size_t)a_rbs * KT1 + kt) * 512 + (tid & 31) * 16;
        cp16(a_dst0 + off, asrc, a_ok ? 16 : 0);
        const char* bsrc = (const char*)g_w1h + ((size_t)(kt * 8 + b_row) * 256 + n0 + b_chunk * 4) * 4;
        cp16(b_dst0 + off, bsrc, 16);
    };

    #pragma unroll
    for (int s = 0; s < S - 1; s++) {
        load_stage(s, s);
        asm volatile("cp.async.commit_group;" ::: "memory");
    }

    for (int kt = 0; kt < KT1; kt++) {
        asm volatile("cp.async.wait_group %0;" :: "n"(S - 2) : "memory");
        __syncthreads();

        int nk = kt + S - 1;
        if (nk < KT1) load_stage(nk, nk % S);
        asm volatile("cp.async.commit_group;" ::: "memory");

        uint32_t As = smb + (uint32_t)((kt % S) * STG_B);
        uint32_t Bs = As + A_BYTES;

        uint32_t a[2][4], b[8][2];
        #pragma unroll
        for (int mt = 0; mt < 2; mt++) {
            uint32_t addr = As + (uint32_t)(((wm >> 4) + mt) * 512 + lane * 16);
            asm volatile("ld.shared.v4.b32 {%0,%1,%2,%3}, [%4];"
                : "=r"(a[mt][0]), "=r"(a[mt][1]), "=r"(a[mt][2]), "=r"(a[mt][3]) : "r"(addr));
        }
        #pragma unroll
        for (int nt = 0; nt < 8; nt++) {
            int ccol = wn + nt * 8 + g;
            uint32_t ad = Bs + (uint32_t)(tig * 544 + ccol * 4);
            asm volatile("ld.shared.b32 %0, [%1];" : "=r"(b[nt][0]) : "r"(ad));
            asm volatile("ld.shared.b32 %0, [%1];" : "=r"(b[nt][1]) : "r"(ad + 4 * 544));
        }
        #pragma unroll
        for (int mt = 0; mt < 2; mt++)
            #pragma unroll
            for (int nt = 0; nt < 8; nt++)
                mma_f16(c[mt][nt], a[mt], b[nt]);
    }

    #pragma unroll
    for (int mt = 0; mt < 2; mt++) {
        int r0 = m0 + wm + mt * 16 + g;
        #pragma unroll
        for (int nt = 0; nt < 8; nt++) {
            int col = n0 + wn + nt * 8 + 2 * tig;
            if (r0 < NN)
                *(float2*)(C + (size_t)r0 * FHID + col) = make_float2(c[mt][nt][0], c[mt][nt][1]);
            if (r0 + 8 < NN)
                *(float2*)(C + (size_t)(r0 + 8) * FHID + col) = make_float2(c[mt][nt][2], c[mt][nt][3]);
        }
    }
}

// ================= GEMM2: tf32 (proven path) =================
template <int NMAT, int KA, int KTILES, int WM, int WN>
__global__ __launch_bounds__(WM * WN * 32, 2)
void mma_gemm_kernel(const float* __restrict__ A, const float* __restrict__ B,
                     float* __restrict__ C) {
    constexpr int S = 4;
    constexpr int THREADS = WM * WN * 32;
    constexpr int BLOCKN = WN * 64;
    constexpr int MT = 128 / WM / 16;
    constexpr int AS_STRIDE = 20;
    constexpr int BS_STRIDE = BLOCKN + 8;
    constexpr int A_FLOATS = 128 * AS_STRIDE;
    constexpr int B_FLOATS = 16 * BS_STRIDE;
    constexpr int STG = A_FLOATS + B_FLOATS;
    constexpr int FA = 2048 / THREADS;
    constexpr int FB = 16 * BLOCKN / THREADS;

    extern __shared__ float smf[];
    uint32_t smb = smem_u32(smf);

    int tid  = threadIdx.x;
    int lane = tid & 31;
    int w    = tid >> 5;
    int g    = lane >> 2;
    int tig  = lane & 3;
    int wm   = (w % WM) * (16 * MT);
    int wn   = (w / WM) * 64;
    int m0   = blockIdx.y * 128;
    int n0   = blockIdx.x * BLOCKN;

    int a_row  = tid / (16 / FA);
    int a_off  = (tid % (16 / FA)) * FA;
    int a_m    = m0 + a_row;
    bool a_ok  = (a_m < NN);
    const float* Ag = A + (size_t)(a_ok ? a_m : 0) * KA;
    uint32_t a_dst0 = smb + (uint32_t)(a_row * AS_STRIDE + a_off) * 4;

    constexpr int B_TPR = BLOCKN / FB;
    int b_row = tid / B_TPR;
    int b_col = (tid % B_TPR) * FB;
    const float* Bg = B + (size_t)b_row * NMAT + n0 + b_col;
    uint32_t b_dst0 = smb + (uint32_t)(A_FLOATS + b_row * BS_STRIDE + b_col) * 4;

    float c[MT][8][4];
    #pragma unroll
    for (int mt = 0; mt < MT; mt++)
        #pragma unroll
        for (int nt = 0; nt < 8; nt++)
            #pragma unroll
            for (int q = 0; q < 4; q++) c[mt][nt][q] = 0.0f;

    auto load_a = [&](int kt, uint32_t off) {
        const float* ga = Ag + kt * 16 + a_off;
        int sz = a_ok ? 16 : 0;
        cp16(a_dst0 + off, ga, sz);
        if (FA == 8) cp16(a_dst0 + off + 16, ga + 4, sz);
    };
    auto load_b = [&](int kt, uint32_t off) {
        const float* gb = Bg + (size_t)(kt * 16) * NMAT;
        #pragma unroll
        for (int i = 0; i < FB / 4; i++)
            cp16(b_dst0 + off + i * 16, gb + i * 4, 16);
    };

    #pragma unroll
    for (int s = 0; s < S - 1; s++) {
        uint32_t off = (uint32_t)(s * STG) * 4;
        if (s < KTILES) { load_a(s, off); load_b(s, off); }
        asm volatile("cp.async.commit_group;" ::: "memory");
    }

    for (int kt = 0; kt < KTILES; kt++) {
        asm volatile("cp.async.wait_group %0;" :: "n"(S - 2) : "memory");
        __syncthreads();

        {
            int nk = kt + S - 1;
            if (nk < KTILES) {
                uint32_t off = (uint32_t)((nk % S) * STG) * 4;
                load_a(nk, off);
                load_b(nk, off);
            }
            asm volatile("cp.async.commit_group;" ::: "memory");
        }

        const float* As = smf + (kt % S) * STG;
        const float* Bs = As + A_FLOATS;

        #pragma unroll
        for (int kk = 0; kk < 16; kk += 8) {
            uint32_t a[MT][4], b[8][2];
            #pragma unroll
            for (int mt = 0; mt < MT; mt++) {
                int r = wm + mt * 16 + g;
                a[mt][0] = __float_as_uint(As[r * AS_STRIDE + kk + tig]);
                a[mt][1] = __float_as_uint(As[(r + 8) * AS_STRIDE + kk + tig]);
                a[mt][2] = __float_as_uint(As[r * AS_STRIDE + kk + tig + 4]);
                a[mt][3] = __float_as_uint(As[(r + 8) * AS_STRIDE + kk + tig + 4]);
            }
            #pragma unroll
            for (int nt = 0; nt < 8; nt++) {
                int ccol = wn + nt * 8 + g;
                b[nt][0] = __float_as_uint(Bs[(kk + tig) * BS_STRIDE + ccol]);
                b[nt][1] = __float_as_uint(Bs[(kk + tig + 4) * BS_STRIDE + ccol]);
            }
            #pragma unroll
            for (int mt = 0; mt < MT; mt++)
                #pragma unroll
                for (int nt = 0; nt < 8; nt++)
                    mma_tf32(c[mt][nt], a[mt], b[nt]);
        }
    }

    #pragma unroll
    for (int mt = 0; mt < MT; mt++) {
        int r0 = m0 + wm + mt * 16 + g;
        #pragma unroll
        for (int nt = 0; nt < 8; nt++) {
            int col = n0 + wn + nt * 8 + 2 * tig;
            if (r0 < NN)
                *(float2*)(C + (size_t)r0 * NMAT + col) = make_float2(c[mt][nt][0], c[mt][nt][1]);
            if (r0 + 8 < NN)
                *(float2*)(C + (size_t)(r0 + 8) * NMAT + col) = make_float2(c[mt][nt][2], c[mt][nt][3]);
        }
    }
}

// ================= fused aggregate + bias + BN + ELU (layer 1, F=256) =================
__device__ __forceinline__ float elu1(float x) { return x > 0.0f ? x : expm1f(x); }

__global__ __launch_bounds__(256)
void aggregate1_kernel(const float* __restrict__ bias,
                       const float* __restrict__ bnw, const float* __restrict__ bnb,
                       const float* __restrict__ bnm, const float* __restrict__ bnv) {
    const float* h = (const float*)g_h1;
    float* out = (float*)g_act1;
    constexpr int F = FHID;

    int warp = (blockIdx.x * blockDim.x + threadIdx.x) >> 5;
    int lane = threadIdx.x & 31;
    if (warp >= NN) return;
    int node = warp;

    float4 acc0, acc1;
    {
        const float4* hn = (const float4*)(h + (size_t)node * F);
        float idg = g_invdeg[node];
        float4 v0 = hn[lane], v1 = hn[lane + 32];
        acc0 = make_float4(v0.x * idg, v0.y * idg, v0.z * idg, v0.w * idg);
        acc1 = make_float4(v1.x * idg, v1.y * idg, v1.z * idg, v1.w * idg);
    }

    int beg = g_offs[node];
    int end = g_offs[node + 1];
    int j = beg;
    for (; j + 4 <= end; j += 4) {
        int2 e0 = g_csr[j], e1 = g_csr[j + 1], e2 = g_csr[j + 2], e3 = g_csr[j + 3];
        const float4* p0 = (const float4*)(h + (size_t)e0.x * F);
        const float4* p1 = (const float4*)(h + (size_t)e1.x * F);
        const float4* p2 = (const float4*)(h + (size_t)e2.x * F);
        const float4* p3 = (const float4*)(h + (size_t)e3.x * F);
        float4 a0 = p0[lane], b0 = p0[lane + 32];
        float4 a1 = p1[lane], b1 = p1[lane + 32];
        float4 a2 = p2[lane], b2 = p2[lane + 32];
        float4 a3 = p3[lane], b3 = p3[lane + 32];
        float c0 = __int_as_float(e0.y), c1 = __int_as_float(e1.y);
        float c2 = __int_as_float(e2.y), c3 = __int_as_float(e3.y);
        acc0.x += a0.x * c0; acc0.y += a0.y * c0; acc0.z += a0.z * c0; acc0.w += a0.w * c0;
        acc1.x += b0.x * c0; acc1.y += b0.y * c0; acc1.z += b0.z * c0; acc1.w += b0.w * c0;
        acc0.x += a1.x * c1; acc0.y += a1.y * c1; acc0.z += a1.z * c1; acc0.w += a1.w * c1;
        acc1.x += b1.x * c1; acc1.y += b1.y * c1; acc1.z += b1.z * c1; acc1.w += b1.w * c1;
        acc0.x += a2.x * c2; acc0.y += a2.y * c2; acc0.z += a2.z * c2; acc0.w += a2.w * c2;
        acc1.x += b2.x * c2; acc1.y += b2.y * c2; acc1.z += b2.z * c2; acc1.w += b2.w * c2;
        acc0.x += a3.x * c3; acc0.y += a3.y * c3; acc0.z += a3.z * c3; acc0.w += a3.w * c3;
        acc1.x += b3.x * c3; acc1.y += b3.y * c3; acc1.z += b3.z * c3; acc1.w += b3.w * c3;
    }
    for (; j < end; j++) {
        int2 e = g_csr[j];
        float cc = __int_as_float(e.y);
        const float4* hs = (const float4*)(h + (size_t)e.x * F);
        float4 a = hs[lane], b = hs[lane + 32];
        acc0.x += a.x * cc; acc0.y += a.y * cc; acc0.z += a.z * cc; acc0.w += a.w * cc;
        acc1.x += b.x * cc; acc1.y += b.y * cc; acc1.z += b.z * cc; acc1.w += b.w * cc;
    }

    #pragma unroll
    for (int t = 0; t < 2; t++) {
        float4 acc = (t == 0) ? acc0 : acc1;
        int f = (lane + 32 * t) * 4;
        float4 bb = *(const float4*)(bias + f);
        float4 w  = *(const float4*)(bnw + f);
        float4 b2 = *(const float4*)(bnb + f);
        float4 mn = *(const float4*)(bnm + f);
        float4 vr = *(const float4*)(bnv + f);
        float4 o;
        o.x = tf32r(elu1((acc.x + bb.x - mn.x) * rsqrtf(vr.x + BN_EPS) * w.x + b2.x));
        o.y = tf32r(elu1((acc.y + bb.y - mn.y) * rsqrtf(vr.y + BN_EPS) * w.y + b2.y));
        o.z = tf32r(elu1((acc.z + bb.z - mn.z) * rsqrtf(vr.z + BN_EPS) * w.z + b2.z));
        o.w = tf32r(elu1((acc.w + bb.w - mn.w) * rsqrtf(vr.w + BN_EPS) * w.w + b2.w));
        ((float4*)(out + (size_t)node * F))[lane + 32 * t] = o;
    }
}

// ===== layer 2 aggregate + BN + ELU, fused with softmax head (F=128) =====
__global__ __launch_bounds__(256)
void aggregate2_head_kernel(const float* __restrict__ bias,
                            const float* __restrict__ bnw, const float* __restrict__ bnb,
                            const float* __restrict__ bnm, const float* __restrict__ bnv,
                            const float* __restrict__ Wp, const float* __restrict__ bp,
                            float* __restrict__ out_h, float* __restrict__ out_z) {
    constexpr int F = FOUT;
    __shared__ float sW[F * NCLS];
    __shared__ float sbp[NCLS];
    for (int i = threadIdx.x; i < F * NCLS; i += blockDim.x) sW[i] = Wp[i];
    if (threadIdx.x < NCLS) sbp[threadIdx.x] = bp[threadIdx.x];
    __syncthreads();

    const float* h = (const float*)g_h2;
    int warp = (blockIdx.x * blockDim.x + threadIdx.x) >> 5;
    int lane = threadIdx.x & 31;
    if (warp >= NN) return;
    int node = warp;

    float4 acc;
    {
        float4 v = ((const float4*)(h + (size_t)node * F))[lane];
        float idg = g_invdeg[node];
        acc = make_float4(v.x * idg, v.y * idg, v.z * idg, v.w * idg);
    }

    int beg = g_offs[node];
    int end = g_offs[node + 1];
    int j = beg;
    for (; j + 4 <= end; j += 4) {
        int2 e0 = g_csr[j], e1 = g_csr[j + 1], e2 = g_csr[j + 2], e3 = g_csr[j + 3];
        float4 a0 = ((const float4*)(h + (size_t)e0.x * F))[lane];
        float4 a1 = ((const float4*)(h + (size_t)e1.x * F))[lane];
        float4 a2 = ((const float4*)(h + (size_t)e2.x * F))[lane];
        float4 a3 = ((const float4*)(h + (size_t)e3.x * F))[lane];
        float c0 = __int_as_float(e0.y), c1 = __int_as_float(e1.y);
        float c2 = __int_as_float(e2.y), c3 = __int_as_float(e3.y);
        acc.x += a0.x * c0; acc.y += a0.y * c0; acc.z += a0.z * c0; acc.w += a0.w * c0;
        acc.x += a1.x * c1; acc.y += a1.y * c1; acc.z += a1.z * c1; acc.w += a1.w * c1;
        acc.x += a2.x * c2; acc.y += a2.y * c2; acc.z += a2.z * c2; acc.w += a2.w * c2;
        acc.x += a3.x * c3; acc.y += a3.y * c3; acc.z += a3.z * c3; acc.w += a3.w * c3;
    }
    for (; j < end; j++) {
        int2 e = g_csr[j];
        float cc = __int_as_float(e.y);
        float4 v = ((const float4*)(h + (size_t)e.x * F))[lane];
        acc.x += v.x * cc; acc.y += v.y * cc; acc.z += v.z * cc; acc.w += v.w * cc;
    }

    int f = lane * 4;
    float4 bb = *(const float4*)(bias + f);
    float4 w  = *(const float4*)(bnw + f);
    float4 b2 = *(const float4*)(bnb + f);
    float4 mn = *(const float4*)(bnm + f);
    float4 vr = *(const float4*)(bnv + f);
    float4 o;
    o.x = elu1((acc.x + bb.x - mn.x) * rsqrtf(vr.x + BN_EPS) * w.x + b2.x);
    o.y = elu1((acc.y + bb.y - mn.y) * rsqrtf(vr.y + BN_EPS) * w.y + b2.y);
    o.z = elu1((acc.z + bb.z - mn.z) * rsqrtf(vr.z + BN_EPS) * w.z + b2.z);
    o.w = elu1((acc.w + bb.w - mn.w) * rsqrtf(vr.w + BN_EPS) * w.w + b2.w);
    ((float4*)(out_h + (size_t)node * F))[lane] = o;

    float p[NCLS];
    #pragma unroll
    for (int k = 0; k < NCLS; k++)
        p[k] = o.x * sW[(f + 0) * NCLS + k] + o.y * sW[(f + 1) * NCLS + k]
             + o.z * sW[(f + 2) * NCLS + k] + o.w * sW[(f + 3) * NCLS + k];
    #pragma unroll
    for (int off = 16; off > 0; off >>= 1)
        #pragma unroll
        for (int k = 0; k < NCLS; k++)
            p[k] += __shfl_xor_sync(0xffffffffu, p[k], off);

    #pragma unroll
    for (int k = 0; k < NCLS; k++) p[k] += sbp[k];
    float m = p[0];
    #pragma unroll
    for (int k = 1; k < NCLS; k++) m = fmaxf(m, p[k]);
    float ssum = 0.0f;
    #pragma unroll
    for (int k = 0; k < NCLS; k++) { p[k] = expf(p[k] - m); ssum += p[k]; }
    float inv = 1.0f / ssum;
    if (lane < NCLS) out_z[(size_t)node * NCLS + lane] = p[lane] * inv;
}

// ================= host =================
extern "C" void kernel_launch(void* const* d_in, const int* in_sizes, int n_in,
                              void* d_out, int out_size) {
    const float* x    = (const float*)d_in[0];
    const int*   ei   = (const int*)d_in[1];
    const float* W1   = (const float*)d_in[2];
    const float* b1   = (const float*)d_in[3];
    const float* bn1w = (const float*)d_in[4];
    const float* bn1b = (const float*)d_in[5];
    const float* bn1m = (const float*)d_in[6];
    const float* bn1v = (const float*)d_in[7];
    const float* W2   = (const float*)d_in[8];
    const float* b2   = (const float*)d_in[9];
    const float* bn2w = (const float*)d_in[10];
    const float* bn2b = (const float*)d_in[11];
    const float* bn2m = (const float*)d_in[12];
    const float* bn2v = (const float*)d_in[13];
    const float* Wp   = (const float*)d_in[14];
    const float* bp   = (const float*)d_in[15];

    const int* src = ei;
    const int* dst = ei + NE;

    float* out_h = (float*)d_out;
    float* out_z = out_h + (size_t)NN * FOUT;

    void *p_w2r, *p_act1, *p_h1, *p_h2;
    cudaGetSymbolAddress(&p_w2r,  g_w2r);
    cudaGetSymbolAddress(&p_act1, g_act1);
    cudaGetSymbolAddress(&p_h1,   g_h1);
    cudaGetSymbolAddress(&p_h2,   g_h2);

    constexpr int SMEM_G1 = 6 * (4096 + 8 * 544);                // 50688
    constexpr int SMEM_G2 = 4 * (128 * 20 + 16 * 136) * 4;       // 75776

    static cudaStream_t s_side = nullptr;
    static cudaEvent_t ev_fork = nullptr, ev_join = nullptr;
    if (!s_side) {
        cudaStreamCreateWithFlags(&s_side, cudaStreamNonBlocking);
        cudaEventCreateWithFlags(&ev_fork, cudaEventDisableTiming);
        cudaEventCreateWithFlags(&ev_join, cudaEventDisableTiming);
        cudaFuncSetAttribute(gemm1_fp16_kernel,
                             cudaFuncAttributeMaxDynamicSharedMemorySize, SMEM_G1);
        cudaFuncSetAttribute(mma_gemm_kernel<FOUT, FHID, FHID / 16, 4, 2>,
                             cudaFuncAttributeMaxDynamicSharedMemorySize, SMEM_G2);
    }

    const int NODE_BLKS = (NN + 255) / 256;
    const int EDGE_BLKS = (NE + 255) / 256;
    const int SCAN_BLKS = (NN + 1023) / 1024;
    const int MTILES    = (NN + 127) / 128;
    const int XH_THREADS = NRB * KT1 * 32;

    // ---- fork ----
    cudaEventRecord(ev_fork, 0);
    cudaStreamWaitEvent(s_side, ev_fork, 0);

    // enqueue order keeps GEMM1 as 4th launch (ncu sample slot):
    // #0 pad_xh (main), #1 round_w1h (main), #2 zero (side), #3 GEMM1 (main)
    pad_xh_kernel<<<(XH_THREADS + 255) / 256, 256>>>(x);
    round_w1h_kernel<<<((KPAD1 / 2) * FHID + 255) / 256, 256>>>(W1);
    zero_cnt_kernel<<<NODE_BLKS, 256, 0, s_side>>>();

    gemm1_fp16_kernel<<<dim3(2, MTILES), 256, SMEM_G1>>>((float*)p_h1);

    // rest of CSR build + W2 rounding on side stream
    count_deg_kernel<<<EDGE_BLKS, 256, 0, s_side>>>(dst);
    scan_block_kernel<<<SCAN_BLKS, 1024, 0, s_side>>>();
    scan_bsum_kernel<<<1, 64, 0, s_side>>>(SCAN_BLKS);
    scan_add_kernel<<<SCAN_BLKS, 1024, 0, s_side>>>();
    fill_csr_kernel<<<EDGE_BLKS, 256, 0, s_side>>>(src, dst);
    round_w2_kernel<<<(FHID * FOUT + 255) / 256, 256, 0, s_side>>>(W2);
    cudaEventRecord(ev_join, s_side);

    // ---- join: aggregation needs CSR ----
    cudaStreamWaitEvent(0, ev_join, 0);

    aggregate1_kernel<<<(NN * 32) / 256, 256>>>(b1, bn1w, bn1b, bn1m, bn1v);

    mma_gemm_kernel<FOUT, FHID, FHID / 16, 4, 2>
        <<<dim3(1, MTILES), 256, SMEM_G2>>>((const float*)p_act1, (const float*)p_w2r, (float*)p_h2);

    aggregate2_head_kernel<<<(NN * 32) / 256, 256>>>(b2, bn2w, bn2b, bn2m, bn2v,
                                                     Wp, bp, out_h, out_z);
}

// round 11
// speedup vs baseline: 1.7108x; 1.0454x over previous
#include <cuda_runtime.h>
#include <cuda_fp16.h>
#include <math.h>
#include <stdint.h>

#define NN   50000
#define NE   800000
#define FIN  1433
#define KPAD1 1440
#define KT1  90            // KPAD1/16
#define NRB  3125          // NN/16 row-blocks (exact)
#define FHID 256
#define FOUT 128
#define NCLS 7
#define BN_EPS 1e-5f

// ---------------- scratch (device globals; no runtime allocation) ----------------
__device__ int   g_cnt[NN];
__device__ int   g_offs[NN + 1];
__device__ int   g_cur[NN];
__device__ int   g_bsum[64];
__device__ int2  g_csr[NE];
__device__ float g_dinv[NN];
__device__ float g_invdeg[NN];
// x as fp16 in mma-fragment-permuted tiles (see pad_xh_kernel)
__device__ __half2 g_xh[(size_t)NRB * KT1 * 128];
// W1 as fp16, kp-pair interleaved: g_w1h[kp*256+n] = {W1[2kp][n], W1[2kp+1][n]}
__device__ __half2 g_w1h[(KPAD1 / 2) * FHID];
__device__ float g_w2r[(size_t)FHID * FOUT];
__device__ __half2 g_h1h[(size_t)NN * (FHID / 2)];   // x @ W1, fp16
__device__ float g_act1[(size_t)NN * FHID];          // ELU(BN(agg1)), tf32-rounded fp32
__device__ __half2 g_h2h[(size_t)NN * (FOUT / 2)];   // act1 @ W2, fp16

// ================= helpers =================
__device__ __forceinline__ uint32_t smem_u32(const void* p) {
    uint32_t a;
    asm("{ .reg .u64 t; cvta.to.shared.u64 t, %1; cvt.u32.u64 %0, t; }" : "=r"(a) : "l"(p));
    return a;
}

__device__ __forceinline__ float tf32r(float x) {
    uint32_t u;
    asm("cvt.rna.tf32.f32 %0, %1;" : "=r"(u) : "f"(x));
    return __uint_as_float(u);
}

__device__ __forceinline__ void cp16(uint32_t dst, const void* src, int srcsize) {
    asm volatile("cp.async.cg.shared.global [%0], [%1], 16, %2;"
                 :: "r"(dst), "l"(src), "r"(srcsize) : "memory");
}

__device__ __forceinline__ void mma_f16(float* c, const uint32_t* a, const uint32_t* b) {
    asm volatile(
        "mma.sync.aligned.m16n8k16.row.col.f32.f16.f16.f32 "
        "{%0,%1,%2,%3}, {%4,%5,%6,%7}, {%8,%9}, {%0,%1,%2,%3};"
        : "+f"(c[0]), "+f"(c[1]), "+f"(c[2]), "+f"(c[3])
        : "r"(a[0]), "r"(a[1]), "r"(a[2]), "r"(a[3]), "r"(b[0]), "r"(b[1]));
}

__device__ __forceinline__ void mma_tf32(float* c, const uint32_t* a, const uint32_t* b) {
    asm volatile(
        "mma.sync.aligned.m16n8k8.row.col.f32.tf32.tf32.f32 "
        "{%0,%1,%2,%3}, {%4,%5,%6,%7}, {%8,%9}, {%0,%1,%2,%3};"
        : "+f"(c[0]), "+f"(c[1]), "+f"(c[2]), "+f"(c[3])
        : "r"(a[0]), "r"(a[1]), "r"(a[2]), "r"(a[3]), "r"(b[0]), "r"(b[1]));
}

// ================= preprocessing =================
__global__ __launch_bounds__(256)
void pad_xh_kernel(const float* __restrict__ x) {
    int idx = blockIdx.x * blockDim.x + threadIdx.x;
    if (idx >= NRB * KT1 * 32) return;
    int lane = idx & 31;
    int tile = idx >> 5;
    int kt = tile % KT1;
    int rb = tile / KT1;
    int g = lane >> 2, tig = lane & 3;
    int row0 = rb * 16 + g;
    int k0 = kt * 16 + 2 * tig;
    const float* xr0 = x + (size_t)row0 * FIN;
    const float* xr1 = xr0 + (size_t)8 * FIN;

    float a0 = (k0     < FIN) ? xr0[k0]     : 0.0f;
    float a1 = (k0 + 1 < FIN) ? xr0[k0 + 1] : 0.0f;
    float b0 = (k0     < FIN) ? xr1[k0]     : 0.0f;
    float b1 = (k0 + 1 < FIN) ? xr1[k0 + 1] : 0.0f;
    int k8 = k0 + 8;
    float a2 = (k8     < FIN) ? xr0[k8]     : 0.0f;
    float a3 = (k8 + 1 < FIN) ? xr0[k8 + 1] : 0.0f;
    float b2 = (k8     < FIN) ? xr1[k8]     : 0.0f;
    float b3 = (k8 + 1 < FIN) ? xr1[k8 + 1] : 0.0f;

    __half2* dst = g_xh + (size_t)tile * 128 + lane * 4;
    dst[0] = __floats2half2_rn(a0, a1);
    dst[1] = __floats2half2_rn(b0, b1);
    dst[2] = __floats2half2_rn(a2, a3);
    dst[3] = __floats2half2_rn(b2, b3);
}

__global__ void round_w1h_kernel(const float* __restrict__ W1) {
    int idx = blockIdx.x * blockDim.x + threadIdx.x;
    if (idx >= (KPAD1 / 2) * FHID) return;
    int kp = idx >> 8;
    int n = idx & 255;
    int k0 = 2 * kp;
    float lo = (k0     < FIN) ? W1[(size_t)k0 * FHID + n]       : 0.0f;
    float hi = (k0 + 1 < FIN) ? W1[(size_t)(k0 + 1) * FHID + n] : 0.0f;
    g_w1h[idx] = __floats2half2_rn(lo, hi);
}

__global__ void round_w2_kernel(const float* __restrict__ W2) {
    int idx = blockIdx.x * blockDim.x + threadIdx.x;
    if (idx >= FHID * FOUT) return;
    g_w2r[idx] = tf32r(W2[idx]);
}

// ================= CSR build =================
__global__ void zero_cnt_kernel() {
    int i = blockIdx.x * blockDim.x + threadIdx.x;
    if (i < NN) g_cnt[i] = 0;
}

__global__ void count_deg_kernel(const int* __restrict__ dst) {
    int e = blockIdx.x * blockDim.x + threadIdx.x;
    if (e < NE) atomicAdd(&g_cnt[dst[e]], 1);
}

__global__ __launch_bounds__(1024)
void scan_block_kernel() {
    __shared__ int ws[32];
    int t = threadIdx.x, b = blockIdx.x;
    int i = b * 1024 + t;
    int v = (i < NN) ? g_cnt[i] : 0;
    if (i < NN) {
        float d = (float)v + 1.0f;
        g_dinv[i]   = rsqrtf(d);
        g_invdeg[i] = 1.0f / d;
    }
    int lane = t & 31, w = t >> 5;
    int x = v;
    #pragma unroll
    for (int o = 1; o < 32; o <<= 1) {
        int y = __shfl_up_sync(0xffffffffu, x, o);
        if (lane >= o) x += y;
    }
    if (lane == 31) ws[w] = x;
    __syncthreads();
    if (w == 0) {
        int s = ws[lane];
        #pragma unroll
        for (int o = 1; o < 32; o <<= 1) {
            int y = __shfl_up_sync(0xffffffffu, s, o);
            if (lane >= o) s += y;
        }
        ws[lane] = s;
    }
    __syncthreads();
    int pre = (w > 0) ? ws[w - 1] : 0;
    if (i < NN) g_offs[i] = pre + x - v;
    if (t == 1023) g_bsum[b] = pre + x;
}

__global__ void scan_bsum_kernel(int nblk) {
    __shared__ int s[64];
    int t = threadIdx.x;
    s[t] = (t < nblk) ? g_bsum[t] : 0;
    __syncthreads();
    if (t == 0) {
        int acc = 0;
        for (int i = 0; i < nblk; i++) { int v = s[i]; s[i] = acc; acc += v; }
    }
    __syncthreads();
    if (t < nblk) g_bsum[t] = s[t];
}

__global__ __launch_bounds__(1024)
void scan_add_kernel() {
    int t = threadIdx.x, b = blockIdx.x;
    int i = b * 1024 + t;
    if (i < NN) {
        int o = g_offs[i] + g_bsum[b];
        g_offs[i] = o;
        g_cur[i]  = o;
    }
    if (i == 0) g_offs[NN] = NE;
}

__global__ void fill_csr_kernel(const int* __restrict__ src, const int* __restrict__ dst) {
    int e = blockIdx.x * blockDim.x + threadIdx.x;
    if (e < NE) {
        int s = src[e];
        int d = dst[e];
        int p = atomicAdd(&g_cur[d], 1);
        g_csr[p] = make_int2(s, __float_as_int(g_dinv[s] * g_dinv[d]));
    }
}

// ================= GEMM1: fp16 m16n8k16, fragment-permuted A, fp16 output =================
__global__ __launch_bounds__(256, 2)
void gemm1_fp16_kernel() {
    constexpr int S = 6;
    constexpr int A_BYTES = 4096;
    constexpr int B_BYTES = 8 * 544;
    constexpr int STG_B = A_BYTES + B_BYTES;

    extern __shared__ char sm[];
    uint32_t smb = smem_u32(sm);

    int tid = threadIdx.x, lane = tid & 31, w = tid >> 5;
    int g = lane >> 2, tig = lane & 3;
    int wm = (w & 3) * 32;
    int wn = (w >> 2) * 64;
    int m0 = blockIdx.y * 128;
    int n0 = blockIdx.x * 128;

    int a_tl = tid >> 5;
    int a_rb = (m0 >> 4) + a_tl;
    bool a_ok = (a_rb < NRB);
    int a_rbs = a_ok ? a_rb : 0;
    uint32_t a_dst0 = smb + (uint32_t)(a_tl * 512 + (tid & 31) * 16);

    int b_row = tid >> 5;
    int b_chunk = tid & 31;
    uint32_t b_dst0 = smb + (uint32_t)(A_BYTES + b_row * 544 + b_chunk * 16);

    float c[2][8][4];
    #pragma unroll
    for (int mt = 0; mt < 2; mt++)
        #pragma unroll
        for (int nt = 0; nt < 8; nt++)
            #pragma unroll
            for (int q = 0; q < 4; q++) c[mt][nt][q] = 0.0f;

    auto load_stage = [&](int kt, int slot) {
        uint32_t off = (uint32_t)(slot * STG_B);
        const char* asrc = (const char*)g_xh + ((size_t)a_rbs * KT1 + kt) * 512 + (tid & 31) * 16;
        cp16(a_dst0 + off, asrc, a_ok ? 16 : 0);
        const char* bsrc = (const char*)g_w1h + ((size_t)(kt * 8 + b_row) * 256 + n0 + b_chunk * 4) * 4;
        cp16(b_dst0 + off, bsrc, 16);
    };

    #pragma unroll
    for (int s = 0; s < S - 1; s++) {
        load_stage(s, s);
        asm volatile("cp.async.commit_group;" ::: "memory");
    }

    for (int kt = 0; kt < KT1; kt++) {
        asm volatile("cp.async.wait_group %0;" :: "n"(S - 2) : "memory");
        __syncthreads();

        int nk = kt + S - 1;
        if (nk < KT1) load_stage(nk, nk % S);
        asm volatile("cp.async.commit_group;" ::: "memory");

        uint32_t As = smb + (uint32_t)((kt % S) * STG_B);
        uint32_t Bs = As + A_BYTES;

        uint32_t a[2][4], b[8][2];
        #pragma unroll
        for (int mt = 0; mt < 2; mt++) {
            uint32_t addr = As + (uint32_t)(((wm >> 4) + mt) * 512 + lane * 16);
            asm volatile("ld.shared.v4.b32 {%0,%1,%2,%3}, [%4];"
                : "=r"(a[mt][0]), "=r"(a[mt][1]), "=r"(a[mt][2]), "=r"(a[mt][3]) : "r"(addr));
        }
        #pragma unroll
        for (int nt = 0; nt < 8; nt++) {
            int ccol = wn + nt * 8 + g;
            uint32_t ad = Bs + (uint32_t)(tig * 544 + ccol * 4);
            asm volatile("ld.shared.b32 %0, [%1];" : "=r"(b[nt][0]) : "r"(ad));
            asm volatile("ld.shared.b32 %0, [%1];" : "=r"(b[nt][1]) : "r"(ad + 4 * 544));
        }
        #pragma unroll
        for (int mt = 0; mt < 2; mt++)
            #pragma unroll
            for (int nt = 0; nt < 8; nt++)
                mma_f16(c[mt][nt], a[mt], b[nt]);
    }

    // epilogue: pack to fp16
    #pragma unroll
    for (int mt = 0; mt < 2; mt++) {
        int r0 = m0 + wm + mt * 16 + g;
        #pragma unroll
        for (int nt = 0; nt < 8; nt++) {
            int colh = ((n0 + wn + nt * 8) >> 1) + tig;   // half2 index
            if (r0 < NN)
                g_h1h[(size_t)r0 * (FHID / 2) + colh] = __floats2half2_rn(c[mt][nt][0], c[mt][nt][1]);
            if (r0 + 8 < NN)
                g_h1h[(size_t)(r0 + 8) * (FHID / 2) + colh] = __floats2half2_rn(c[mt][nt][2], c[mt][nt][3]);
        }
    }
}

// ================= GEMM2: tf32, fp16 output =================
template <int NMAT, int KA, int KTILES, int WM, int WN>
__global__ __launch_bounds__(WM * WN * 32, 2)
void mma_gemm_kernel(const float* __restrict__ A, const float* __restrict__ B) {
    constexpr int S = 4;
    constexpr int THREADS = WM * WN * 32;
    constexpr int BLOCKN = WN * 64;
    constexpr int MT = 128 / WM / 16;
    constexpr int AS_STRIDE = 20;
    constexpr int BS_STRIDE = BLOCKN + 8;
    constexpr int A_FLOATS = 128 * AS_STRIDE;
    constexpr int B_FLOATS = 16 * BS_STRIDE;
    constexpr int STG = A_FLOATS + B_FLOATS;
    constexpr int FA = 2048 / THREADS;
    constexpr int FB = 16 * BLOCKN / THREADS;

    extern __shared__ float smf[];
    uint32_t smb = smem_u32(smf);

    int tid  = threadIdx.x;
    int lane = tid & 31;
    int w    = tid >> 5;
    int g    = lane >> 2;
    int tig  = lane & 3;
    int wm   = (w % WM) * (16 * MT);
    int wn   = (w / WM) * 64;
    int m0   = blockIdx.y * 128;
    int n0   = blockIdx.x * BLOCKN;

    int a_row  = tid / (16 / FA);
    int a_off  = (tid % (16 / FA)) * FA;
    int a_m    = m0 + a_row;
    bool a_ok  = (a_m < NN);
    const float* Ag = A + (size_t)(a_ok ? a_m : 0) * KA;
    uint32_t a_dst0 = smb + (uint32_t)(a_row * AS_STRIDE + a_off) * 4;

    constexpr int B_TPR = BLOCKN / FB;
    int b_row = tid / B_TPR;
    int b_col = (tid % B_TPR) * FB;
    const float* Bg = B + (size_t)b_row * NMAT + n0 + b_col;
    uint32_t b_dst0 = smb + (uint32_t)(A_FLOATS + b_row * BS_STRIDE + b_col) * 4;

    float c[MT][8][4];
    #pragma unroll
    for (int mt = 0; mt < MT; mt++)
        #pragma unroll
        for (int nt = 0; nt < 8; nt++)
            #pragma unroll
            for (int q = 0; q < 4; q++) c[mt][nt][q] = 0.0f;

    auto load_a = [&](int kt, uint32_t off) {
        const float* ga = Ag + kt * 16 + a_off;
        int sz = a_ok ? 16 : 0;
        cp16(a_dst0 + off, ga, sz);
        if (FA == 8) cp16(a_dst0 + off + 16, ga + 4, sz);
    };
    auto load_b = [&](int kt, uint32_t off) {
        const float* gb = Bg + (size_t)(kt * 16) * NMAT;
        #pragma unroll
        for (int i = 0; i < FB / 4; i++)
            cp16(b_dst0 + off + i * 16, gb + i * 4, 16);
    };

    #pragma unroll
    for (int s = 0; s < S - 1; s++) {
        uint32_t off = (uint32_t)(s * STG) * 4;
        if (s < KTILES) { load_a(s, off); load_b(s, off); }
        asm volatile("cp.async.commit_group;" ::: "memory");
    }

    for (int kt = 0; kt < KTILES; kt++) {
        asm volatile("cp.async.wait_group %0;" :: "n"(S - 2) : "memory");
        __syncthreads();

        {
            int nk = kt + S - 1;
            if (nk < KTILES) {
                uint32_t off = (uint32_t)((nk % S) * STG) * 4;
                load_a(nk, off);
                load_b(nk, off);
            }
            asm volatile("cp.async.commit_group;" ::: "memory");
        }

        const float* As = smf + (kt % S) * STG;
        const float* Bs = As + A_FLOATS;

        #pragma unroll
        for (int kk = 0; kk < 16; kk += 8) {
            uint32_t a[MT][4], b[8][2];
            #pragma unroll
            for (int mt = 0; mt < MT; mt++) {
                int r = wm + mt * 16 + g;
                a[mt][0] = __float_as_uint(As[r * AS_STRIDE + kk + tig]);
                a[mt][1] = __float_as_uint(As[(r + 8) * AS_STRIDE + kk + tig]);
                a[mt][2] = __float_as_uint(As[r * AS_STRIDE + kk + tig + 4]);
                a[mt][3] = __float_as_uint(As[(r + 8) * AS_STRIDE + kk + tig + 4]);
            }
            #pragma unroll
            for (int nt = 0; nt < 8; nt++) {
                int ccol = wn + nt * 8 + g;
                b[nt][0] = __float_as_uint(Bs[(kk + tig) * BS_STRIDE + ccol]);
                b[nt][1] = __float_as_uint(Bs[(kk + tig + 4) * BS_STRIDE + ccol]);
            }
            #pragma unroll
            for (int mt = 0; mt < MT; mt++)
                #pragma unroll
                for (int nt = 0; nt < 8; nt++)
                    mma_tf32(c[mt][nt], a[mt], b[nt]);
        }
    }

    // epilogue: pack to fp16 into g_h2h
    #pragma unroll
    for (int mt = 0; mt < MT; mt++) {
        int r0 = m0 + wm + mt * 16 + g;
        #pragma unroll
        for (int nt = 0; nt < 8; nt++) {
            int colh = ((n0 + wn + nt * 8) >> 1) + tig;
            if (r0 < NN)
                g_h2h[(size_t)r0 * (FOUT / 2) + colh] = __floats2half2_rn(c[mt][nt][0], c[mt][nt][1]);
            if (r0 + 8 < NN)
                g_h2h[(size_t)(r0 + 8) * (FOUT / 2) + colh] = __floats2half2_rn(c[mt][nt][2], c[mt][nt][3]);
        }
    }
}

// ================= fused aggregate + bias + BN + ELU (layer 1, F=256, fp16 gather) =================
__device__ __forceinline__ float elu1(float x) { return x > 0.0f ? x : expm1f(x); }

__device__ __forceinline__ void acc8_h(float* acc, uint4 v, float cc) {
    __half2 h0 = *(__half2*)&v.x, h1 = *(__half2*)&v.y;
    __half2 h2 = *(__half2*)&v.z, h3 = *(__half2*)&v.w;
    float2 f0 = __half22float2(h0), f1 = __half22float2(h1);
    float2 f2 = __half22float2(h2), f3 = __half22float2(h3);
    acc[0] += f0.x * cc; acc[1] += f0.y * cc;
    acc[2] += f1.x * cc; acc[3] += f1.y * cc;
    acc[4] += f2.x * cc; acc[5] += f2.y * cc;
    acc[6] += f3.x * cc; acc[7] += f3.y * cc;
}

__global__ __launch_bounds__(256)
void aggregate1_kernel(const float* __restrict__ bias,
                       const float* __restrict__ bnw, const float* __restrict__ bnb,
                       const float* __restrict__ bnm, const float* __restrict__ bnv) {
    const uint4* h = (const uint4*)g_h1h;   // row = 8 uint4 (32 lanes x 16B = 512B)
    float* out = (float*)g_act1;

    int warp = (blockIdx.x * blockDim.x + threadIdx.x) >> 5;
    int lane = threadIdx.x & 31;
    if (warp >= NN) return;
    int node = warp;

    float acc[8];
    {
        uint4 v = h[(size_t)node * 8 + (lane >> 2)];
        // careful: row = 512B = 32 x 16B chunks... recompute below
    }
    // row of h1h: 128 half2 = 512B = 32 uint4; lane chunk = lane
    {
        uint4 v = ((const uint4*)g_h1h)[(size_t)node * 32 + lane];
        float idg = g_invdeg[node];
        #pragma unroll
        for (int q = 0; q < 8; q++) acc[q] = 0.0f;
        acc8_h(acc, v, idg);
    }

    int beg = g_offs[node];
    int end = g_offs[node + 1];
    int j = beg;
    for (; j + 4 <= end; j += 4) {
        int2 e0 = g_csr[j], e1 = g_csr[j + 1], e2 = g_csr[j + 2], e3 = g_csr[j + 3];
        uint4 v0 = ((const uint4*)g_h1h)[(size_t)e0.x * 32 + lane];
        uint4 v1 = ((const uint4*)g_h1h)[(size_t)e1.x * 32 + lane];
        uint4 v2 = ((const uint4*)g_h1h)[(size_t)e2.x * 32 + lane];
        uint4 v3 = ((const uint4*)g_h1h)[(size_t)e3.x * 32 + lane];
        acc8_h(acc, v0, __int_as_float(e0.y));
        acc8_h(acc, v1, __int_as_float(e1.y));
        acc8_h(acc, v2, __int_as_float(e2.y));
        acc8_h(acc, v3, __int_as_float(e3.y));
    }
    for (; j < end; j++) {
        int2 e = g_csr[j];
        uint4 v = ((const uint4*)g_h1h)[(size_t)e.x * 32 + lane];
        acc8_h(acc, v, __int_as_float(e.y));
    }

    int f = lane * 8;
    #pragma unroll
    for (int t = 0; t < 2; t++) {
        int ff = f + t * 4;
        float4 bb = *(const float4*)(bias + ff);
        float4 w  = *(const float4*)(bnw + ff);
        float4 b2 = *(const float4*)(bnb + ff);
        float4 mn = *(const float4*)(bnm + ff);
        float4 vr = *(const float4*)(bnv + ff);
        float4 o;
        o.x = tf32r(elu1((acc[t * 4 + 0] + bb.x - mn.x) * rsqrtf(vr.x + BN_EPS) * w.x + b2.x));
        o.y = tf32r(elu1((acc[t * 4 + 1] + bb.y - mn.y) * rsqrtf(vr.y + BN_EPS) * w.y + b2.y));
        o.z = tf32r(elu1((acc[t * 4 + 2] + bb.z - mn.z) * rsqrtf(vr.z + BN_EPS) * w.z + b2.z));
        o.w = tf32r(elu1((acc[t * 4 + 3] + bb.w - mn.w) * rsqrtf(vr.w + BN_EPS) * w.w + b2.w));
        *(float4*)(out + (size_t)node * FHID + ff) = o;
    }
}

// ===== layer 2 aggregate + BN + ELU, fused with softmax head (F=128, fp16 gather) =====
__device__ __forceinline__ void acc4_h(float4& acc, uint2 v, float cc) {
    float2 f0 = __half22float2(*(__half2*)&v.x);
    float2 f1 = __half22float2(*(__half2*)&v.y);
    acc.x += f0.x * cc; acc.y += f0.y * cc;
    acc.z += f1.x * cc; acc.w += f1.y * cc;
}

__global__ __launch_bounds__(256)
void aggregate2_head_kernel(const float* __restrict__ bias,
                            const float* __restrict__ bnw, const float* __restrict__ bnb,
                            const float* __restrict__ bnm, const float* __restrict__ bnv,
                            const float* __restrict__ Wp, const float* __restrict__ bp,
                            float* __restrict__ out_h, float* __restrict__ out_z) {
    constexpr int F = FOUT;
    __shared__ float sW[F * NCLS];
    __shared__ float sbp[NCLS];
    for (int i = threadIdx.x; i < F * NCLS; i += blockDim.x) sW[i] = Wp[i];
    if (threadIdx.x < NCLS) sbp[threadIdx.x] = bp[threadIdx.x];
    __syncthreads();

    const uint2* h = (const uint2*)g_h2h;   // row = 32 uint2 (256B)
    int warp = (blockIdx.x * blockDim.x + threadIdx.x) >> 5;
    int lane = threadIdx.x & 31;
    if (warp >= NN) return;
    int node = warp;

    float4 acc = make_float4(0.f, 0.f, 0.f, 0.f);
    acc4_h(acc, h[(size_t)node * 32 + lane], g_invdeg[node]);

    int beg = g_offs[node];
    int end = g_offs[node + 1];
    int j = beg;
    for (; j + 4 <= end; j += 4) {
        int2 e0 = g_csr[j], e1 = g_csr[j + 1], e2 = g_csr[j + 2], e3 = g_csr[j + 3];
        uint2 v0 = h[(size_t)e0.x * 32 + lane];
        uint2 v1 = h[(size_t)e1.x * 32 + lane];
        uint2 v2 = h[(size_t)e2.x * 32 + lane];
        uint2 v3 = h[(size_t)e3.x * 32 + lane];
        acc4_h(acc, v0, __int_as_float(e0.y));
        acc4_h(acc, v1, __int_as_float(e1.y));
        acc4_h(acc, v2, __int_as_float(e2.y));
        acc4_h(acc, v3, __int_as_float(e3.y));
    }
    for (; j < end; j++) {
        int2 e = g_csr[j];
        acc4_h(acc, h[(size_t)e.x * 32 + lane], __int_as_float(e.y));
    }

    int f = lane * 4;
    float4 bb = *(const float4*)(bias + f);
    float4 w  = *(const float4*)(bnw + f);
    float4 b2 = *(const float4*)(bnb + f);
    float4 mn = *(const float4*)(bnm + f);
    float4 vr = *(const float4*)(bnv + f);
    float4 o;
    o.x = elu1((acc.x + bb.x - mn.x) * rsqrtf(vr.x + BN_EPS) * w.x + b2.x);
    o.y = elu1((acc.y + bb.y - mn.y) * rsqrtf(vr.y + BN_EPS) * w.y + b2.y);
    o.z = elu1((acc.z + bb.z - mn.z) * rsqrtf(vr.z + BN_EPS) * w.z + b2.z);
    o.w = elu1((acc.w + bb.w - mn.w) * rsqrtf(vr.w + BN_EPS) * w.w + b2.w);
    ((float4*)(out_h + (size_t)node * F))[lane] = o;

    float p[NCLS];
    #pragma unroll
    for (int k = 0; k < NCLS; k++)
        p[k] = o.x * sW[(f + 0) * NCLS + k] + o.y * sW[(f + 1) * NCLS + k]
             + o.z * sW[(f + 2) * NCLS + k] + o.w * sW[(f + 3) * NCLS + k];
    #pragma unroll
    for (int off = 16; off > 0; off >>= 1)
        #pragma unroll
        for (int k = 0; k < NCLS; k++)
            p[k] += __shfl_xor_sync(0xffffffffu, p[k], off);

    #pragma unroll
    for (int k = 0; k < NCLS; k++) p[k] += sbp[k];
    float m = p[0];
    #pragma unroll
    for (int k = 1; k < NCLS; k++) m = fmaxf(m, p[k]);
    float ssum = 0.0f;
    #pragma unroll
    for (int k = 0; k < NCLS; k++) { p[k] = expf(p[k] - m); ssum += p[k]; }
    float inv = 1.0f / ssum;
    if (lane < NCLS) out_z[(size_t)node * NCLS + lane] = p[lane] * inv;
}

// ================= host =================
extern "C" void kernel_launch(void* const* d_in, const int* in_sizes, int n_in,
                              void* d_out, int out_size) {
    const float* x    = (const float*)d_in[0];
    const int*   ei   = (const int*)d_in[1];
    const float* W1   = (const float*)d_in[2];
    const float* b1   = (const float*)d_in[3];
    const float* bn1w = (const float*)d_in[4];
    const float* bn1b = (const float*)d_in[5];
    const float* bn1m = (const float*)d_in[6];
    const float* bn1v = (const float*)d_in[7];
    const float* W2   = (const float*)d_in[8];
    const float* b2   = (const float*)d_in[9];
    const float* bn2w = (const float*)d_in[10];
    const float* bn2b = (const float*)d_in[11];
    const float* bn2m = (const float*)d_in[12];
    const float* bn2v = (const float*)d_in[13];
    const float* Wp   = (const float*)d_in[14];
    const float* bp   = (const float*)d_in[15];

    const int* src = ei;
    const int* dst = ei + NE;

    float* out_h = (float*)d_out;
    float* out_z = out_h + (size_t)NN * FOUT;

    void *p_w2r, *p_act1;
    cudaGetSymbolAddress(&p_w2r,  g_w2r);
    cudaGetSymbolAddress(&p_act1, g_act1);

    constexpr int SMEM_G1 = 6 * (4096 + 8 * 544);                // 50688
    constexpr int SMEM_G2 = 4 * (128 * 20 + 16 * 136) * 4;       // 75776

    static cudaStream_t s_side = nullptr;
    static cudaEvent_t ev_fork = nullptr, ev_join = nullptr;
    if (!s_side) {
        cudaStreamCreateWithFlags(&s_side, cudaStreamNonBlocking);
        cudaEventCreateWithFlags(&ev_fork, cudaEventDisableTiming);
        cudaEventCreateWithFlags(&ev_join, cudaEventDisableTiming);
        cudaFuncSetAttribute(gemm1_fp16_kernel,
                             cudaFuncAttributeMaxDynamicSharedMemorySize, SMEM_G1);
        cudaFuncSetAttribute(mma_gemm_kernel<FOUT, FHID, FHID / 16, 4, 2>,
                             cudaFuncAttributeMaxDynamicSharedMemorySize, SMEM_G2);
    }

    const int NODE_BLKS = (NN + 255) / 256;
    const int EDGE_BLKS = (NE + 255) / 256;
    const int SCAN_BLKS = (NN + 1023) / 1024;
    const int MTILES    = (NN + 127) / 128;
    const int XH_THREADS = NRB * KT1 * 32;

    // ---- fork ----
    cudaEventRecord(ev_fork, 0);
    cudaStreamWaitEvent(s_side, ev_fork, 0);

    // enqueue order keeps GEMM1 as 4th launch (ncu sample slot)
    pad_xh_kernel<<<(XH_THREADS + 255) / 256, 256>>>(x);
    round_w1h_kernel<<<((KPAD1 / 2) * FHID + 255) / 256, 256>>>(W1);
    zero_cnt_kernel<<<NODE_BLKS, 256, 0, s_side>>>();

    gemm1_fp16_kernel<<<dim3(2, MTILES), 256, SMEM_G1>>>();

    // rest of CSR build + W2 rounding on side stream
    count_deg_kernel<<<EDGE_BLKS, 256, 0, s_side>>>(dst);
    scan_block_kernel<<<SCAN_BLKS, 1024, 0, s_side>>>();
    scan_bsum_kernel<<<1, 64, 0, s_side>>>(SCAN_BLKS);
    scan_add_kernel<<<SCAN_BLKS, 1024, 0, s_side>>>();
    fill_csr_kernel<<<EDGE_BLKS, 256, 0, s_side>>>(src, dst);
    round_w2_kernel<<<(FHID * FOUT + 255) / 256, 256, 0, s_side>>>(W2);
    cudaEventRecord(ev_join, s_side);

    // ---- join: aggregation needs CSR ----
    cudaStreamWaitEvent(0, ev_join, 0);

    aggregate1_kernel<<<(NN * 32) / 256, 256>>>(b1, bn1w, bn1b, bn1m, bn1v);

    mma_gemm_kernel<FOUT, FHID, FHID / 16, 4, 2>
        <<<dim3(1, MTILES), 256, SMEM_G2>>>((const float*)p_act1, (const float*)p_w2r);

    aggregate2_head_kernel<<<(NN * 32) / 256, 256>>>(b2, bn2w, bn2b, bn2m, bn2v,
                                                     Wp, bp, out_h, out_z);
}